// round 1
// baseline (speedup 1.0000x reference)
#include <cuda_runtime.h>
#include <math.h>

#define D 512
#define T 2048
#define NBATCH 32
#define NB 512
#define R (NBATCH*T)            // 65536 rows
#define M_TILE 64
#define NBLOCKS (R/M_TILE)      // 1024
#define NC 128
#define KC 64
#define XS_STRIDE 68            // pad: keeps float4 alignment (mult of 4), bank shift of 4 per k

// ---- scratch (no allocations allowed) ----
__device__ float g_Ct[D*NB];          // transposed codebook [d][code]
__device__ float g_cnorm[NB];
__device__ int   g_hist[NB];
__device__ float g_blockCommit[NBLOCKS];

// ---------------- prep: transpose codebook, cnorm, zero hist ----------------
__global__ void prep_kernel(const float* __restrict__ codebook) {
    int c = blockIdx.x;
    int d = threadIdx.x;
    float v = codebook[c*D + d];
    g_Ct[d*NB + c] = v;
    __shared__ float sbuf[D];
    sbuf[d] = v*v;
    __syncthreads();
    for (int s = D/2; s > 0; s >>= 1) {
        if (d < s) sbuf[d] += sbuf[d+s];
        __syncthreads();
    }
    if (d == 0) { g_cnorm[c] = sbuf[0]; g_hist[c] = 0; }
}

// ---------------- main: normalize + GEMM/argmin + gather-out ----------------
extern __shared__ float smem[];

__global__ __launch_bounds__(256, 1) void vq_main(const float* __restrict__ x,
                                                  const float* __restrict__ codebook,
                                                  float* __restrict__ out) {
    float* Xs        = smem;                          // [512][68]
    float* Cs        = Xs + D*XS_STRIDE;              // [64][128]
    float* cn_s      = Cs + KC*NC;                    // [512]
    float* inv_s     = cn_s + NB;                     // [64]
    float* sumsq_s   = inv_s + M_TILE;                // [64]
    float* normpart  = sumsq_s + M_TILE;              // [4][64]
    float* red_score = normpart + 4*M_TILE;           // [64][16]
    int*   red_idx   = (int*)(red_score + M_TILE*16); // [64][16]
    int*   idx_s     = red_idx + M_TILE*16;           // [64]
    float* commit_red= (float*)(idx_s + M_TILE);      // [64]

    const int tid = threadIdx.x;
    const int blk = blockIdx.x;
    const int rows0 = blk * M_TILE;
    const int nb = rows0 / T;
    const int t0 = rows0 % T;
    const float* xblk = x + (size_t)nb*D*T + t0;

    // codebook norms to smem
    for (int i = tid; i < NB; i += 256) cn_s[i] = g_cnorm[i];

    // load X tile: Xs[d][m] = x[nb, d, t0+m]  (coalesced float4 along t)
    {
        const int tq = tid & 15;       // which float4 along t
        const int dr = tid >> 4;       // 16 d-rows per pass
        #pragma unroll
        for (int it = 0; it < D/16; ++it) {
            int d = it*16 + dr;
            float4 v = *reinterpret_cast<const float4*>(xblk + (size_t)d*T + tq*4);
            *reinterpret_cast<float4*>(&Xs[d*XS_STRIDE + tq*4]) = v;
        }
    }
    __syncthreads();

    // per-row sum of squares (4 threads per row)
    {
        const int part = tid >> 6;     // 0..3
        const int m = tid & 63;
        float s = 0.f;
        #pragma unroll 8
        for (int k = part*128; k < part*128 + 128; ++k) {
            float v = Xs[k*XS_STRIDE + m];
            s = fmaf(v, v, s);
        }
        normpart[part*64 + m] = s;
    }
    __syncthreads();
    if (tid < M_TILE) {
        float s = normpart[tid] + normpart[64+tid] + normpart[128+tid] + normpart[192+tid];
        sumsq_s[tid] = s;
        inv_s[tid] = 1.0f / fmaxf(sqrtf(s), 1e-12f);
    }
    __syncthreads();

    const int mg = tid & 15;   // row group: rows 4*mg..4*mg+3
    const int ng = tid >> 4;   // col group: codes 8*ng..8*ng+7 (within chunk)
    float inv4[4];
    #pragma unroll
    for (int i = 0; i < 4; ++i) inv4[i] = inv_s[4*mg + i];

    float bestS[4]; int bestI[4];
    #pragma unroll
    for (int i = 0; i < 4; ++i) { bestS[i] = 3.4e38f; bestI[i] = 0; }

    for (int cc = 0; cc < NB/NC; ++cc) {
        float acc[4][8];
        #pragma unroll
        for (int i=0;i<4;i++)
            #pragma unroll
            for (int j=0;j<8;j++) acc[i][j]=0.f;

        for (int kc = 0; kc < D/KC; ++kc) {
            __syncthreads();
            // load Cs[k][c] = Ct[kc*64+k][cc*128+c]  (coalesced float4)
            {
                const int c4 = (tid & 31)*4;
                const int k0 = tid >> 5;   // 0..7
                #pragma unroll
                for (int kk = k0; kk < KC; kk += 8)
                    *reinterpret_cast<float4*>(&Cs[kk*NC + c4]) =
                        *reinterpret_cast<const float4*>(&g_Ct[(size_t)(kc*KC+kk)*NB + cc*NC + c4]);
            }
            __syncthreads();
            #pragma unroll 8
            for (int k = 0; k < KC; ++k) {
                float4 a  = *reinterpret_cast<const float4*>(&Xs[(kc*KC + k)*XS_STRIDE + 4*mg]);
                float4 b0 = *reinterpret_cast<const float4*>(&Cs[k*NC + 8*ng]);
                float4 b1 = *reinterpret_cast<const float4*>(&Cs[k*NC + 8*ng + 4]);
                float av[4] = {a.x,a.y,a.z,a.w};
                float bv[8] = {b0.x,b0.y,b0.z,b0.w,b1.x,b1.y,b1.z,b1.w};
                #pragma unroll
                for (int i=0;i<4;i++)
                    #pragma unroll
                    for (int j=0;j<8;j++)
                        acc[i][j] = fmaf(av[i], bv[j], acc[i][j]);
            }
        }
        // epilogue: score = cnorm - 2*inv*dot ; argmin
        #pragma unroll
        for (int i=0;i<4;i++) {
            #pragma unroll
            for (int j=0;j<8;j++) {
                int code = cc*NC + 8*ng + j;
                float score = cn_s[code] - 2.0f*inv4[i]*acc[i][j];
                if (score < bestS[i]) { bestS[i] = score; bestI[i] = code; }
            }
        }
    }

    // cross-thread argmin reduce (16 col-groups per row)
    #pragma unroll
    for (int i=0;i<4;i++) {
        int m = 4*mg + i;
        red_score[m*16 + ng] = bestS[i];
        red_idx[m*16 + ng]   = bestI[i];
    }
    __syncthreads();
    if (tid < M_TILE) {
        float bs = red_score[tid*16]; int bi = red_idx[tid*16];
        #pragma unroll
        for (int g=1; g<16; ++g) {
            float s = red_score[tid*16+g]; int ii = red_idx[tid*16+g];
            if (s < bs || (s == bs && ii < bi)) { bs = s; bi = ii; }
        }
        idx_s[tid] = bi;
        float inv = inv_s[tid];
        // ||xf - c||^2 = ||xf||^2 + (cnorm - 2*inv*dot)  per row (summed over D)
        commit_red[tid] = fmaf(sumsq_s[tid]*inv, inv, bs);
        atomicAdd(&g_hist[bi], 1);
    }
    __syncthreads();
    if (tid == 0) {
        float s = 0.f;
        for (int i=0;i<M_TILE;i++) s += commit_red[i];
        g_blockCommit[blk] = s;
    }

    // gather codebook rows for this tile into Xs[d][m] (coalesced global read)
    for (int e = tid; e < M_TILE*D; e += 256) {
        int m = e >> 9;        // e / 512
        int d = e & 511;
        Xs[d*XS_STRIDE + m] = codebook[(size_t)idx_s[m]*D + d];
    }
    __syncthreads();

    // write out[n, d, t] coalesced along t
    {
        const int tq = tid & 15;
        const int dr = tid >> 4;
        float* oblk = out + (size_t)nb*D*T + t0;
        #pragma unroll
        for (int it = 0; it < D/16; ++it) {
            int d = it*16 + dr;
            float4 v = *reinterpret_cast<const float4*>(&Xs[d*XS_STRIDE + 4*tq]);
            *reinterpret_cast<float4*>(oblk + (size_t)d*T + tq*4) = v;
        }
    }
}

// ---------------- finalize: perplexity + commit mean scalars ----------------
__global__ void finalize_kernel(float* __restrict__ out) {
    __shared__ double sbuf[512];
    int t = threadIdx.x;
    float prob = (float)g_hist[t] / 65536.0f;
    float term = prob * logf(prob + 1e-7f);
    sbuf[t] = (double)term;
    __syncthreads();
    for (int s=256; s>0; s>>=1) { if (t<s) sbuf[t]+=sbuf[t+s]; __syncthreads(); }
    double psum = sbuf[0];
    __syncthreads();
    double c = 0.0;
    for (int i = t; i < NBLOCKS; i += 512) c += (double)g_blockCommit[i];
    sbuf[t] = c;
    __syncthreads();
    for (int s=256; s>0; s>>=1) { if (t<s) sbuf[t]+=sbuf[t+s]; __syncthreads(); }
    if (t == 0) {
        double commit_mean = sbuf[0] / ((double)R * (double)D);
        out[(size_t)R*D]     = (float)commit_mean;
        out[(size_t)R*D + 1] = expf((float)(-psum));
    }
}

// ---------------- launch ----------------
extern "C" void kernel_launch(void* const* d_in, const int* in_sizes, int n_in,
                              void* d_out, int out_size) {
    const float* x        = (const float*)d_in[0];
    const float* codebook = (const float*)d_in[1];
    float* out = (float*)d_out;

    int smem_bytes = (D*XS_STRIDE + KC*NC + NB + M_TILE + M_TILE + 4*M_TILE
                      + M_TILE*16 + M_TILE*16 + M_TILE + M_TILE) * (int)sizeof(float);
    cudaFuncSetAttribute(vq_main, cudaFuncAttributeMaxDynamicSharedMemorySize, smem_bytes);

    prep_kernel<<<NB, D>>>(codebook);
    vq_main<<<NBLOCKS, 256, smem_bytes>>>(x, codebook, out);
    finalize_kernel<<<1, 512>>>(out);
}

// round 3
// speedup vs baseline: 1.5393x; 1.5393x over previous
#include <cuda_runtime.h>
#include <cuda_bf16.h>
#include <math.h>
#include <stdint.h>

#define D 512
#define T 2048
#define NBATCH 32
#define NB 512
#define R (NBATCH*T)          // 65536 rows
#define M_TILE 128
#define CTAS (R/M_TILE)       // 512
#define OUT_MTILE 64
#define OUT_BLOCKS (R/OUT_MTILE)

// -------- scratch (__device__ globals; no allocations allowed) --------
__device__ __align__(16) __nv_bfloat16 g_Xh[(size_t)R*D];   // x hi, row-major
__device__ __align__(16) __nv_bfloat16 g_Xl[(size_t)R*D];   // x lo
__device__ __align__(16) __nv_bfloat16 g_Cbh[NB*D];         // codebook hi (K-major)
__device__ __align__(16) __nv_bfloat16 g_Cbl[NB*D];         // codebook lo
__device__ float g_cnorm[NB];
__device__ float g_sspart[8][R];      // deterministic sumsq partials per d-tile
__device__ int   g_hist[NB];
__device__ int   g_idx[R];
__device__ float g_blockCommit[CTAS];

// -------- helpers --------
__device__ __forceinline__ uint32_t smem_u32(const void* p){
    uint32_t a;
    asm("{ .reg .u64 t; cvta.to.shared.u64 t, %1; cvt.u32.u64 %0, t; }" : "=r"(a) : "l"(p));
    return a;
}
__device__ __forceinline__ void ldsm4(uint32_t (&r)[4], uint32_t addr){
    asm volatile("ldmatrix.sync.aligned.m8n8.x4.shared.b16 {%0,%1,%2,%3}, [%4];"
        : "=r"(r[0]), "=r"(r[1]), "=r"(r[2]), "=r"(r[3]) : "r"(addr));
}
__device__ __forceinline__ void mma_bf16(float (&c)[4], const uint32_t (&a)[4],
                                         uint32_t b0, uint32_t b1){
    asm volatile("mma.sync.aligned.m16n8k16.row.col.f32.bf16.bf16.f32 "
        "{%0,%1,%2,%3}, {%4,%5,%6,%7}, {%8,%9}, {%0,%1,%2,%3};"
        : "+f"(c[0]), "+f"(c[1]), "+f"(c[2]), "+f"(c[3])
        : "r"(a[0]), "r"(a[1]), "r"(a[2]), "r"(a[3]), "r"(b0), "r"(b1));
}
__device__ __forceinline__ void cpasync16(uint32_t dst, const void* src){
    asm volatile("cp.async.cg.shared.global [%0], [%1], 16;" :: "r"(dst), "l"(src) : "memory");
}
#define CP_COMMIT() asm volatile("cp.async.commit_group;" ::: "memory")
#define CP_WAIT1()  asm volatile("cp.async.wait_group 1;" ::: "memory")

// ---------------- prep: codebook -> bf16 hi/lo, cnorm, zero hist ----------------
__global__ void prep_cb(const float* __restrict__ codebook) {
    int c = blockIdx.x, d = threadIdx.x;
    float v = codebook[c*D + d];
    __nv_bfloat16 h = __float2bfloat16_rn(v);
    __nv_bfloat16 l = __float2bfloat16_rn(v - __bfloat162float(h));
    g_Cbh[c*D + d] = h;
    g_Cbl[c*D + d] = l;
    __shared__ float sbuf[D];
    sbuf[d] = v*v;
    __syncthreads();
    for (int s = 256; s > 0; s >>= 1) {
        if (d < s) sbuf[d] += sbuf[d+s];
        __syncthreads();
    }
    if (d == 0) { g_cnorm[c] = sbuf[0]; g_hist[c] = 0; }
}

// ---------------- transpose x -> row-major bf16 hi/lo + sumsq partials ----------------
__global__ __launch_bounds__(256) void xpose(const float* __restrict__ x) {
    __shared__ float s[64][65];
    int tt = blockIdx.x;    // t-tile (32)
    int dt = blockIdx.y;    // d-tile (8)
    int n  = blockIdx.z;    // batch (32)
    int tid = threadIdx.x;
    const float* xp = x + ((size_t)n*D + dt*64)*T + tt*64;
    for (int i = tid; i < 1024; i += 256) {
        int r = i >> 4, q = i & 15;
        float4 v = *reinterpret_cast<const float4*>(xp + (size_t)r*T + q*4);
        s[r][q*4+0] = v.x; s[r][q*4+1] = v.y; s[r][q*4+2] = v.z; s[r][q*4+3] = v.w;
    }
    __syncthreads();
    if (tid < 64) {   // deterministic partial sumsq per t over these 64 d's
        float acc = 0.f;
        #pragma unroll 16
        for (int k = 0; k < 64; ++k) { float v = s[k][tid]; acc = fmaf(v, v, acc); }
        g_sspart[dt][(size_t)n*T + tt*64 + tid] = acc;
    }
    uint32_t* oh = reinterpret_cast<uint32_t*>(g_Xh);
    uint32_t* ol = reinterpret_cast<uint32_t*>(g_Xl);
    for (int i = tid; i < 2048; i += 256) {
        int tr = i >> 5, q = i & 31;
        float a = s[2*q][tr], b = s[2*q+1][tr];
        __nv_bfloat16 ah = __float2bfloat16_rn(a), bh = __float2bfloat16_rn(b);
        __nv_bfloat16 al = __float2bfloat16_rn(a - __bfloat162float(ah));
        __nv_bfloat16 bl = __float2bfloat16_rn(b - __bfloat162float(bh));
        size_t row = (size_t)n*T + tt*64 + tr;
        size_t base = (row*D + dt*64)/2 + q;
        oh[base] = (uint32_t)__bfloat16_as_ushort(ah) | ((uint32_t)__bfloat16_as_ushort(bh) << 16);
        ol[base] = (uint32_t)__bfloat16_as_ushort(al) | ((uint32_t)__bfloat16_as_ushort(bl) << 16);
    }
}

// ---------------- main: HMMA bf16-split GEMM + argmin epilogue ----------------
#define SM_RED_S 4096
#define SM_RED_I 20480
#define SM_STAGE 36864
#define STAGE_SZ 49152
#define SMEM_TOTAL 135168

__global__ __launch_bounds__(256, 1) void vq_main(const float* __restrict__ x,
                                                  const float* __restrict__ codebook) {
    extern __shared__ char smem[];
    const uint32_t sb = smem_u32(smem);
    float* cn_s  = reinterpret_cast<float*>(smem);
    float* inv_s = reinterpret_cast<float*>(smem + 2048);
    float* sq_s  = reinterpret_cast<float*>(smem + 2560);
    float* cm_s  = reinterpret_cast<float*>(smem + 3072);
    float* red_s = reinterpret_cast<float*>(smem + SM_RED_S);
    int*   red_i = reinterpret_cast<int*>(smem + SM_RED_I);

    const int tid  = threadIdx.x;
    const int lane = tid & 31, wid = tid >> 5;
    const int wm = wid & 1, wn = wid >> 1;
    const int blk  = blockIdx.x;
    const int row0 = blk * M_TILE;

    for (int i = tid; i < NB; i += 256) cn_s[i] = g_cnorm[i];
    if (tid < 128) {
        float sq = 0.f;
        #pragma unroll
        for (int j = 0; j < 8; ++j) sq += g_sspart[j][row0 + tid];
        sq_s[tid]  = sq;
        inv_s[tid] = 1.0f / fmaxf(sqrtf(sq), 1e-12f);
    }
    __syncthreads();

    // chunk prefetch (double buffered cp.async)
    auto prefetch = [&](int c, int n0, int stg){
        int kc = c & 7;
        const __nv_bfloat16* As = (c < 16) ? g_Xh : g_Xl;
        const __nv_bfloat16* Bs = (c < 8) ? g_Cbh : ((c < 16) ? g_Cbl : g_Cbh);
        uint32_t abase = sb + SM_STAGE + stg*STAGE_SZ;
        uint32_t bbase = abase + 16384;
        #pragma unroll
        for (int t = 0; t < 4; ++t) {          // A: 128 x 64 bf16
            int i = tid + t*256;
            int r = i >> 3, q = i & 7;
            uint32_t off = (uint32_t)(r*128) + (((uint32_t)q*16) ^ (((uint32_t)(r & 7))*16));
            cpasync16(abase + off, As + (size_t)(row0 + r)*D + kc*64 + q*8);
        }
        #pragma unroll
        for (int t = 0; t < 8; ++t) {          // B: 256 x 64 bf16
            int i = tid + t*256;
            int r = i >> 3, q = i & 7;
            uint32_t off = (uint32_t)(r*128) + (((uint32_t)q*16) ^ (((uint32_t)(r & 7))*16));
            cpasync16(bbase + off, Bs + (size_t)(n0 + r)*D + kc*64 + q*8);
        }
    };

    // per-row/slot running top-2 (kept across both N passes)
    float bs1[8], bs2[8]; int bi1[8], bi2[8];
    #pragma unroll
    for (int s = 0; s < 8; ++s) { bs1[s] = 3.4e38f; bs2[s] = 3.4e38f; bi1[s] = 0; bi2[s] = 0; }

    // fragment address bases
    const int rA = wm*64 + (lane & 7) + ((lane >> 3) & 1)*8;
    const uint32_t rowA = (uint32_t)rA * 128;
    const uint32_t kxA  = ((uint32_t)(lane >> 4)) * 16;
    const uint32_t swA  = ((uint32_t)(rA & 7)) * 16;
    const int rBl = (lane & 7) + (lane >> 4)*8;
    const uint32_t kxB  = (((uint32_t)(lane >> 3)) & 1) * 16;
    const uint32_t swB  = ((uint32_t)(lane & 7)) * 16;
    const uint32_t rowB = (uint32_t)(wn*64 + rBl) * 128;

    for (int pass = 0; pass < 2; ++pass) {
        const int n0 = pass * 256;
        float acc[4][8][4];
        #pragma unroll
        for (int a = 0; a < 4; ++a)
            #pragma unroll
            for (int b = 0; b < 8; ++b)
                #pragma unroll
                for (int e = 0; e < 4; ++e) acc[a][b][e] = 0.f;

        prefetch(0, n0, 0);
        CP_COMMIT();
        for (int c = 0; c < 24; ++c) {
            if (c < 23) prefetch(c + 1, n0, (c + 1) & 1);
            CP_COMMIT();
            CP_WAIT1();
            __syncthreads();
            uint32_t ab = sb + SM_STAGE + (c & 1)*STAGE_SZ;
            uint32_t bb = ab + 16384;
            #pragma unroll
            for (int ks = 0; ks < 4; ++ks) {
                uint32_t bf[4][4];
                #pragma unroll
                for (int nt2 = 0; nt2 < 4; ++nt2)
                    ldsm4(bf[nt2], bb + rowB + (uint32_t)nt2*2048 + (((uint32_t)ks*32 + kxB) ^ swB));
                #pragma unroll
                for (int mt = 0; mt < 4; ++mt) {
                    uint32_t aa[4];
                    ldsm4(aa, ab + rowA + (uint32_t)mt*2048 + (((uint32_t)ks*32 + kxA) ^ swA));
                    #pragma unroll
                    for (int nt2 = 0; nt2 < 4; ++nt2) {
                        mma_bf16(acc[mt][2*nt2],   aa, bf[nt2][0], bf[nt2][1]);
                        mma_bf16(acc[mt][2*nt2+1], aa, bf[nt2][2], bf[nt2][3]);
                    }
                }
            }
            __syncthreads();
        }

        // epilogue: fold this pass's 256 codes into running top-2 per row slot
        #pragma unroll
        for (int mt = 0; mt < 4; ++mt) {
            #pragma unroll
            for (int h = 0; h < 2; ++h) {
                const int slot = mt*2 + h;
                const int row = wm*64 + mt*16 + (lane >> 2) + h*8;
                const float m2inv = -2.0f * inv_s[row];
                #pragma unroll
                for (int nt = 0; nt < 8; ++nt) {
                    int code = n0 + wn*64 + nt*8 + (lane & 3)*2;
                    float s0 = fmaf(m2inv, acc[mt][nt][h*2+0], cn_s[code]);
                    float s1 = fmaf(m2inv, acc[mt][nt][h*2+1], cn_s[code+1]);
                    if (s0 < bs1[slot]) { bs2[slot]=bs1[slot]; bi2[slot]=bi1[slot]; bs1[slot]=s0; bi1[slot]=code; }
                    else if (s0 < bs2[slot]) { bs2[slot]=s0; bi2[slot]=code; }
                    if (s1 < bs1[slot]) { bs2[slot]=bs1[slot]; bi2[slot]=bi1[slot]; bs1[slot]=s1; bi1[slot]=code+1; }
                    else if (s1 < bs2[slot]) { bs2[slot]=s1; bi2[slot]=code+1; }
                }
            }
        }
    }

    // candidate reduction: 16 candidate slices x top-2 per row
    __syncthreads();
    #pragma unroll
    for (int mt = 0; mt < 4; ++mt) {
        #pragma unroll
        for (int h = 0; h < 2; ++h) {
            const int slot = mt*2 + h;
            const int row = wm*64 + mt*16 + (lane >> 2) + h*8;
            const int cb = (wn*4 + (lane & 3))*2;
            red_s[row*32 + cb]     = bs1[slot]; red_i[row*32 + cb]     = bi1[slot];
            red_s[row*32 + cb + 1] = bs2[slot]; red_i[row*32 + cb + 1] = bi2[slot];
        }
    }
    __syncthreads();

    if (tid < 128) {
        float s1 = 3.4e38f, s2 = s1, s3 = s1, s4 = s1;
        int i1 = 0, i2 = 0, i3 = 0, i4 = 0;
        for (int c = 0; c < 32; ++c) {
            float s = red_s[tid*32 + c]; int ii = red_i[tid*32 + c];
            if (s < s1 || (s == s1 && ii < i1)) { s4=s3;i4=i3; s3=s2;i3=i2; s2=s1;i2=i1; s1=s;i1=ii; }
            else if (s < s2 || (s == s2 && ii < i2)) { s4=s3;i4=i3; s3=s2;i3=i2; s2=s;i2=ii; }
            else if (s < s3 || (s == s3 && ii < i3)) { s4=s3;i4=i3; s3=s;i3=ii; }
            else if (s < s4 || (s == s4 && ii < i4)) { s4=s;i4=ii; }
        }
        const float inv = inv_s[tid], sq = sq_s[tid];
        float bestS = s1; int bestI = i1;
        if (s2 - s1 < 1e-4f) {   // exact fp32 rescue of top-4 candidates
            int grow = row0 + tid;
            int nb_ = grow / T, tl = grow % T;
            const float* xr = x + (size_t)nb_*D*T + tl;
            const float* c1p = codebook + (size_t)i1*D;
            const float* c2p = codebook + (size_t)i2*D;
            const float* c3p = codebook + (size_t)i3*D;
            const float* c4p = codebook + (size_t)i4*D;
            float d1 = 0.f, d2 = 0.f, d3 = 0.f, d4 = 0.f;
            for (int d = 0; d < D; ++d) {
                float xv = xr[(size_t)d*T];
                d1 = fmaf(xv, c1p[d], d1); d2 = fmaf(xv, c2p[d], d2);
                d3 = fmaf(xv, c3p[d], d3); d4 = fmaf(xv, c4p[d], d4);
            }
            float e1 = fmaf(-2.0f*inv, d1, cn_s[i1]);
            float e2 = fmaf(-2.0f*inv, d2, cn_s[i2]);
            float e3 = fmaf(-2.0f*inv, d3, cn_s[i3]);
            float e4 = fmaf(-2.0f*inv, d4, cn_s[i4]);
            bestS = e1; bestI = i1;
            if (e2 < bestS || (e2 == bestS && i2 < bestI)) { bestS = e2; bestI = i2; }
            if (e3 < bestS || (e3 == bestS && i3 < bestI)) { bestS = e3; bestI = i3; }
            if (e4 < bestS || (e4 == bestS && i4 < bestI)) { bestS = e4; bestI = i4; }
        }
        g_idx[row0 + tid] = bestI;
        cm_s[tid] = fmaf(sq*inv, inv, bestS);
        atomicAdd(&g_hist[bestI], 1);
    }
    __syncthreads();
    if (tid == 0) {
        float s = 0.f;
        for (int i = 0; i < 128; ++i) s += cm_s[i];
        g_blockCommit[blk] = s;
    }
}

// ---------------- output: gather codebook rows, transpose, write (n,d,t) ----------------
__global__ __launch_bounds__(256) void out_kernel(const float* __restrict__ codebook,
                                                  float* __restrict__ out) {
    extern __shared__ float Xs[];   // [512][68]
    __shared__ int idx_s[OUT_MTILE];
    const int tid = threadIdx.x, blk = blockIdx.x;
    const int rows0 = blk * OUT_MTILE;
    const int nb_ = rows0 / T, t0 = rows0 % T;
    if (tid < OUT_MTILE) idx_s[tid] = g_idx[rows0 + tid];
    __syncthreads();
    for (int e = tid; e < OUT_MTILE*D; e += 256) {
        int m = e >> 9, d = e & 511;
        Xs[d*68 + m] = codebook[(size_t)idx_s[m]*D + d];
    }
    __syncthreads();
    float* ob = out + (size_t)nb_*D*T + t0;
    const int tq = tid & 15, dr = tid >> 4;
    #pragma unroll
    for (int itr = 0; itr < D/16; ++itr) {
        int d = itr*16 + dr;
        float4 v = *reinterpret_cast<float4*>(&Xs[d*68 + 4*tq]);
        *reinterpret_cast<float4*>(ob + (size_t)d*T + tq*4) = v;
    }
}

// ---------------- finalize: perplexity + commit mean ----------------
__global__ void finalize_kernel(float* __restrict__ out) {
    __shared__ double sbuf[512];
    int t = threadIdx.x;
    float prob = (float)g_hist[t] / 65536.0f;
    sbuf[t] = (double)(prob * logf(prob + 1e-7f));
    __syncthreads();
    for (int s = 256; s > 0; s >>= 1) { if (t < s) sbuf[t] += sbuf[t+s]; __syncthreads(); }
    double psum = sbuf[0];
    __syncthreads();
    sbuf[t] = (t < CTAS) ? (double)g_blockCommit[t] : 0.0;
    __syncthreads();
    for (int s = 256; s > 0; s >>= 1) { if (t < s) sbuf[t] += sbuf[t+s]; __syncthreads(); }
    if (t == 0) {
        out[(size_t)R*D]     = (float)(sbuf[0] / ((double)R * (double)D));
        out[(size_t)R*D + 1] = expf((float)(-psum));
    }
}

// ---------------- launch ----------------
extern "C" void kernel_launch(void* const* d_in, const int* in_sizes, int n_in,
                              void* d_out, int out_size) {
    const float* x        = (const float*)d_in[0];
    const float* codebook = (const float*)d_in[1];
    float* out = (float*)d_out;

    cudaFuncSetAttribute(vq_main, cudaFuncAttributeMaxDynamicSharedMemorySize, SMEM_TOTAL);
    cudaFuncSetAttribute(out_kernel, cudaFuncAttributeMaxDynamicSharedMemorySize, 512*68*4);

    prep_cb<<<NB, D>>>(codebook);
    dim3 tg(T/64, D/64, NBATCH);
    xpose<<<tg, 256>>>(x);
    vq_main<<<CTAS, 256, SMEM_TOTAL>>>(x, codebook);
    out_kernel<<<OUT_BLOCKS, 256, 512*68*4>>>(codebook, out);
    finalize_kernel<<<1, 512>>>(out);
}

// round 4
// speedup vs baseline: 1.8222x; 1.1838x over previous
#include <cuda_runtime.h>
#include <cuda_bf16.h>
#include <math.h>
#include <stdint.h>

#define D 512
#define T 2048
#define NBATCH 32
#define NB 512
#define R (NBATCH*T)          // 65536 rows
#define M_TILE 128
#define CTAS (R/M_TILE)       // 512

// -------- scratch (__device__ globals; no allocations allowed) --------
__device__ __align__(16) __nv_bfloat16 g_Xh[(size_t)R*D];   // x hi, row-major
__device__ __align__(16) __nv_bfloat16 g_Xl[(size_t)R*D];   // x lo
__device__ __align__(16) __nv_bfloat16 g_Cbh[NB*D];         // codebook hi (K-major)
__device__ __align__(16) __nv_bfloat16 g_Cbl[NB*D];         // codebook lo
__device__ float g_cnorm[NB];
__device__ float g_sspart[8][R];      // deterministic sumsq partials per d-tile
__device__ int   g_hist[NB];
__device__ int   g_idx[R];
__device__ float g_blockCommit[CTAS];

// -------- helpers --------
__device__ __forceinline__ uint32_t smem_u32(const void* p){
    uint32_t a;
    asm("{ .reg .u64 t; cvta.to.shared.u64 t, %1; cvt.u32.u64 %0, t; }" : "=r"(a) : "l"(p));
    return a;
}
__device__ __forceinline__ void ldsm4(uint32_t (&r)[4], uint32_t addr){
    asm volatile("ldmatrix.sync.aligned.m8n8.x4.shared.b16 {%0,%1,%2,%3}, [%4];"
        : "=r"(r[0]), "=r"(r[1]), "=r"(r[2]), "=r"(r[3]) : "r"(addr));
}
__device__ __forceinline__ void mma_bf16(float (&c)[4], const uint32_t (&a)[4],
                                         uint32_t b0, uint32_t b1){
    asm volatile("mma.sync.aligned.m16n8k16.row.col.f32.bf16.bf16.f32 "
        "{%0,%1,%2,%3}, {%4,%5,%6,%7}, {%8,%9}, {%0,%1,%2,%3};"
        : "+f"(c[0]), "+f"(c[1]), "+f"(c[2]), "+f"(c[3])
        : "r"(a[0]), "r"(a[1]), "r"(a[2]), "r"(a[3]), "r"(b0), "r"(b1));
}
__device__ __forceinline__ void cpasync16(uint32_t dst, const void* src){
    asm volatile("cp.async.cg.shared.global [%0], [%1], 16;" :: "r"(dst), "l"(src) : "memory");
}
#define CP_COMMIT() asm volatile("cp.async.commit_group;" ::: "memory")
#define CP_WAIT1()  asm volatile("cp.async.wait_group 1;" ::: "memory")

// ---------------- prep: codebook -> bf16 hi/lo, cnorm, zero hist ----------------
__global__ void prep_cb(const float* __restrict__ codebook) {
    int c = blockIdx.x, d = threadIdx.x;
    float v = codebook[c*D + d];
    __nv_bfloat16 h = __float2bfloat16_rn(v);
    __nv_bfloat16 l = __float2bfloat16_rn(v - __bfloat162float(h));
    g_Cbh[c*D + d] = h;
    g_Cbl[c*D + d] = l;
    __shared__ float sbuf[D];
    sbuf[d] = v*v;
    __syncthreads();
    for (int s = 256; s > 0; s >>= 1) {
        if (d < s) sbuf[d] += sbuf[d+s];
        __syncthreads();
    }
    if (d == 0) { g_cnorm[c] = sbuf[0]; g_hist[c] = 0; }
}

// ---------------- transpose x -> row-major bf16 hi/lo + sumsq partials ----------------
__global__ __launch_bounds__(256) void xpose(const float* __restrict__ x) {
    __shared__ float s[64][65];
    int tt = blockIdx.x;
    int dt = blockIdx.y;
    int n  = blockIdx.z;
    int tid = threadIdx.x;
    const float* xp = x + ((size_t)n*D + dt*64)*T + tt*64;
    for (int i = tid; i < 1024; i += 256) {
        int r = i >> 4, q = i & 15;
        float4 v = *reinterpret_cast<const float4*>(xp + (size_t)r*T + q*4);
        s[r][q*4+0] = v.x; s[r][q*4+1] = v.y; s[r][q*4+2] = v.z; s[r][q*4+3] = v.w;
    }
    __syncthreads();
    if (tid < 64) {
        float acc = 0.f;
        #pragma unroll 16
        for (int k = 0; k < 64; ++k) { float v = s[k][tid]; acc = fmaf(v, v, acc); }
        g_sspart[dt][(size_t)n*T + tt*64 + tid] = acc;
    }
    uint32_t* oh = reinterpret_cast<uint32_t*>(g_Xh);
    uint32_t* ol = reinterpret_cast<uint32_t*>(g_Xl);
    for (int i = tid; i < 2048; i += 256) {
        int tr = i >> 5, q = i & 31;
        float a = s[2*q][tr], b = s[2*q+1][tr];
        __nv_bfloat16 ah = __float2bfloat16_rn(a), bh = __float2bfloat16_rn(b);
        __nv_bfloat16 al = __float2bfloat16_rn(a - __bfloat162float(ah));
        __nv_bfloat16 bl = __float2bfloat16_rn(b - __bfloat162float(bh));
        size_t row = (size_t)n*T + tt*64 + tr;
        size_t base = (row*D + dt*64)/2 + q;
        oh[base] = (uint32_t)__bfloat16_as_ushort(ah) | ((uint32_t)__bfloat16_as_ushort(bh) << 16);
        ol[base] = (uint32_t)__bfloat16_as_ushort(al) | ((uint32_t)__bfloat16_as_ushort(bl) << 16);
    }
}

// ---------------- main: HMMA bf16-split GEMM + argmin epilogue ----------------
#define SM_STAGE 4096
#define A_H 0
#define A_L 16384
#define B_H 32768
#define B_L 65536
#define STAGE_SZ 98304
#define SMEM_TOTAL (SM_STAGE + 2*STAGE_SZ)   // 200704

__global__ __launch_bounds__(256, 1) void vq_main(const float* __restrict__ x,
                                                  const float* __restrict__ codebook) {
    extern __shared__ char smem[];
    const uint32_t sb = smem_u32(smem);
    float* cn_s  = reinterpret_cast<float*>(smem);
    float* inv_s = reinterpret_cast<float*>(smem + 2048);
    float* sq_s  = reinterpret_cast<float*>(smem + 2560);
    float* cm_s  = reinterpret_cast<float*>(smem + 3072);
    // reduction arrays overlay stage0 (used only after the mainloop)
    float* red_s = reinterpret_cast<float*>(smem + SM_STAGE);
    int*   red_i = reinterpret_cast<int*>(smem + SM_STAGE + 16384);

    const int tid  = threadIdx.x;
    const int lane = tid & 31, wid = tid >> 5;
    const int wm = wid & 1, wn = wid >> 1;
    const int blk  = blockIdx.x;
    const int row0 = blk * M_TILE;

    for (int i = tid; i < NB; i += 256) cn_s[i] = g_cnorm[i];
    if (tid < 128) {
        float sq = 0.f;
        #pragma unroll
        for (int j = 0; j < 8; ++j) sq += g_sspart[j][row0 + tid];
        sq_s[tid]  = sq;
        inv_s[tid] = 1.0f / fmaxf(sqrtf(sq), 1e-12f);
    }
    __syncthreads();

    // stage carries {Ah, Al, Bh, Bl} for one K-chunk of 64
    auto prefetch = [&](int kc, int n0, int stg){
        uint32_t base = sb + SM_STAGE + stg*STAGE_SZ;
        #pragma unroll
        for (int t = 0; t < 4; ++t) {          // A: 128 x 64 bf16, hi+lo
            int i = tid + t*256;
            int r = i >> 3, q = i & 7;
            uint32_t off = (uint32_t)(r*128) + (((uint32_t)q*16) ^ (((uint32_t)(r & 7))*16));
            size_t gsrc = (size_t)(row0 + r)*D + kc*64 + q*8;
            cpasync16(base + A_H + off, g_Xh + gsrc);
            cpasync16(base + A_L + off, g_Xl + gsrc);
        }
        #pragma unroll
        for (int t = 0; t < 8; ++t) {          // B: 256 x 64 bf16, hi+lo
            int i = tid + t*256;
            int r = i >> 3, q = i & 7;
            uint32_t off = (uint32_t)(r*128) + (((uint32_t)q*16) ^ (((uint32_t)(r & 7))*16));
            size_t gsrc = (size_t)(n0 + r)*D + kc*64 + q*8;
            cpasync16(base + B_H + off, g_Cbh + gsrc);
            cpasync16(base + B_L + off, g_Cbl + gsrc);
        }
    };

    // per-row/slot running top-2 (kept across both N passes)
    float bs1[8], bs2[8]; int bi1[8], bi2[8];
    #pragma unroll
    for (int s = 0; s < 8; ++s) { bs1[s] = 3.4e38f; bs2[s] = 3.4e38f; bi1[s] = 0; bi2[s] = 0; }

    // fragment address bases
    const int rA = wm*64 + (lane & 7) + ((lane >> 3) & 1)*8;
    const uint32_t rowA = (uint32_t)rA * 128;
    const uint32_t kxA  = ((uint32_t)(lane >> 4)) * 16;
    const uint32_t swA  = ((uint32_t)(rA & 7)) * 16;
    const int rBl = (lane & 7) + (lane >> 4)*8;
    const uint32_t kxB  = (((uint32_t)(lane >> 3)) & 1) * 16;
    const uint32_t swB  = ((uint32_t)(lane & 7)) * 16;
    const uint32_t rowB = (uint32_t)(wn*64 + rBl) * 128;

    for (int pass = 0; pass < 2; ++pass) {
        const int n0 = pass * 256;
        float acc[4][8][4];
        #pragma unroll
        for (int a = 0; a < 4; ++a)
            #pragma unroll
            for (int b = 0; b < 8; ++b)
                #pragma unroll
                for (int e = 0; e < 4; ++e) acc[a][b][e] = 0.f;

        prefetch(0, n0, 0);
        CP_COMMIT();
        for (int c = 0; c < 8; ++c) {
            if (c < 7) prefetch(c + 1, n0, (c + 1) & 1);
            CP_COMMIT();
            CP_WAIT1();
            __syncthreads();
            uint32_t ab = sb + SM_STAGE + (c & 1)*STAGE_SZ;

            // sub-pass 1: Ah x Bh  and  Ah x Bl
            #pragma unroll
            for (int ks = 0; ks < 4; ++ks) {
                uint32_t bh[4][4], bl[4][4];
                #pragma unroll
                for (int nt2 = 0; nt2 < 4; ++nt2) {
                    uint32_t boff = rowB + (uint32_t)nt2*2048 + (((uint32_t)ks*32 + kxB) ^ swB);
                    ldsm4(bh[nt2], ab + B_H + boff);
                    ldsm4(bl[nt2], ab + B_L + boff);
                }
                #pragma unroll
                for (int mt = 0; mt < 4; ++mt) {
                    uint32_t aa[4];
                    ldsm4(aa, ab + A_H + rowA + (uint32_t)mt*2048 + (((uint32_t)ks*32 + kxA) ^ swA));
                    #pragma unroll
                    for (int nt2 = 0; nt2 < 4; ++nt2) {
                        mma_bf16(acc[mt][2*nt2],   aa, bh[nt2][0], bh[nt2][1]);
                        mma_bf16(acc[mt][2*nt2+1], aa, bh[nt2][2], bh[nt2][3]);
                        mma_bf16(acc[mt][2*nt2],   aa, bl[nt2][0], bl[nt2][1]);
                        mma_bf16(acc[mt][2*nt2+1], aa, bl[nt2][2], bl[nt2][3]);
                    }
                }
            }
            // sub-pass 2: Al x Bh
            #pragma unroll
            for (int ks = 0; ks < 4; ++ks) {
                uint32_t bh[4][4];
                #pragma unroll
                for (int nt2 = 0; nt2 < 4; ++nt2)
                    ldsm4(bh[nt2], ab + B_H + rowB + (uint32_t)nt2*2048 + (((uint32_t)ks*32 + kxB) ^ swB));
                #pragma unroll
                for (int mt = 0; mt < 4; ++mt) {
                    uint32_t aa[4];
                    ldsm4(aa, ab + A_L + rowA + (uint32_t)mt*2048 + (((uint32_t)ks*32 + kxA) ^ swA));
                    #pragma unroll
                    for (int nt2 = 0; nt2 < 4; ++nt2) {
                        mma_bf16(acc[mt][2*nt2],   aa, bh[nt2][0], bh[nt2][1]);
                        mma_bf16(acc[mt][2*nt2+1], aa, bh[nt2][2], bh[nt2][3]);
                    }
                }
            }
            __syncthreads();
        }

        // epilogue: fold this pass's 256 codes into running top-2 per row slot
        #pragma unroll
        for (int mt = 0; mt < 4; ++mt) {
            #pragma unroll
            for (int h = 0; h < 2; ++h) {
                const int slot = mt*2 + h;
                const int row = wm*64 + mt*16 + (lane >> 2) + h*8;
                const float m2inv = -2.0f * inv_s[row];
                #pragma unroll
                for (int nt = 0; nt < 8; ++nt) {
                    int code = n0 + wn*64 + nt*8 + (lane & 3)*2;
                    float s0 = fmaf(m2inv, acc[mt][nt][h*2+0], cn_s[code]);
                    float s1 = fmaf(m2inv, acc[mt][nt][h*2+1], cn_s[code+1]);
                    if (s0 < bs1[slot]) { bs2[slot]=bs1[slot]; bi2[slot]=bi1[slot]; bs1[slot]=s0; bi1[slot]=code; }
                    else if (s0 < bs2[slot]) { bs2[slot]=s0; bi2[slot]=code; }
                    if (s1 < bs1[slot]) { bs2[slot]=bs1[slot]; bi2[slot]=bi1[slot]; bs1[slot]=s1; bi1[slot]=code+1; }
                    else if (s1 < bs2[slot]) { bs2[slot]=s1; bi2[slot]=code+1; }
                }
            }
        }
    }

    // candidate reduction: 16 candidate slices x top-2 per row (overlays stage0)
    __syncthreads();
    #pragma unroll
    for (int mt = 0; mt < 4; ++mt) {
        #pragma unroll
        for (int h = 0; h < 2; ++h) {
            const int slot = mt*2 + h;
            const int row = wm*64 + mt*16 + (lane >> 2) + h*8;
            const int cb = (wn*4 + (lane & 3))*2;
            red_s[row*32 + cb]     = bs1[slot]; red_i[row*32 + cb]     = bi1[slot];
            red_s[row*32 + cb + 1] = bs2[slot]; red_i[row*32 + cb + 1] = bi2[slot];
        }
    }
    __syncthreads();

    if (tid < 128) {
        float s1 = 3.4e38f, s2 = s1, s3 = s1, s4 = s1;
        int i1 = 0, i2 = 0, i3 = 0, i4 = 0;
        for (int c = 0; c < 32; ++c) {
            float s = red_s[tid*32 + c]; int ii = red_i[tid*32 + c];
            if (s < s1 || (s == s1 && ii < i1)) { s4=s3;i4=i3; s3=s2;i3=i2; s2=s1;i2=i1; s1=s;i1=ii; }
            else if (s < s2 || (s == s2 && ii < i2)) { s4=s3;i4=i3; s3=s2;i3=i2; s2=s;i2=ii; }
            else if (s < s3 || (s == s3 && ii < i3)) { s4=s3;i4=i3; s3=s;i3=ii; }
            else if (s < s4 || (s == s4 && ii < i4)) { s4=s;i4=ii; }
        }
        const float inv = inv_s[tid], sq = sq_s[tid];
        float bestS = s1; int bestI = i1;
        if (s2 - s1 < 1e-4f) {   // exact fp32 rescue of top-4 candidates
            int grow = row0 + tid;
            int nb_ = grow / T, tl = grow % T;
            const float* xr = x + (size_t)nb_*D*T + tl;
            const float* c1p = codebook + (size_t)i1*D;
            const float* c2p = codebook + (size_t)i2*D;
            const float* c3p = codebook + (size_t)i3*D;
            const float* c4p = codebook + (size_t)i4*D;
            float d1 = 0.f, d2 = 0.f, d3 = 0.f, d4 = 0.f;
            for (int d = 0; d < D; ++d) {
                float xv = xr[(size_t)d*T];
                d1 = fmaf(xv, c1p[d], d1); d2 = fmaf(xv, c2p[d], d2);
                d3 = fmaf(xv, c3p[d], d3); d4 = fmaf(xv, c4p[d], d4);
            }
            float e1 = fmaf(-2.0f*inv, d1, cn_s[i1]);
            float e2 = fmaf(-2.0f*inv, d2, cn_s[i2]);
            float e3 = fmaf(-2.0f*inv, d3, cn_s[i3]);
            float e4 = fmaf(-2.0f*inv, d4, cn_s[i4]);
            bestS = e1; bestI = i1;
            if (e2 < bestS || (e2 == bestS && i2 < bestI)) { bestS = e2; bestI = i2; }
            if (e3 < bestS || (e3 == bestS && i3 < bestI)) { bestS = e3; bestI = i3; }
            if (e4 < bestS || (e4 == bestS && i4 < bestI)) { bestS = e4; bestI = i4; }
        }
        g_idx[row0 + tid] = bestI;
        cm_s[tid] = fmaf(sq*inv, inv, bestS);
        atomicAdd(&g_hist[bestI], 1);
    }
    __syncthreads();
    if (tid == 0) {
        float s = 0.f;
        for (int i = 0; i < 128; ++i) s += cm_s[i];
        g_blockCommit[blk] = s;
    }
}

// ---------------- output v2: direct gather-write, full occupancy ----------------
__global__ __launch_bounds__(128) void out_kernel(const float* __restrict__ codebook,
                                                  float* __restrict__ out) {
    const int rows0 = blockIdx.x * 128;          // 128 | T so one n per block
    const int d0 = blockIdx.y * 128;
    const int row = rows0 + threadIdx.x;
    const int n = row / T;
    const int t = row % T;
    const int code = g_idx[row];
    const float4* crow = reinterpret_cast<const float4*>(codebook + (size_t)code*D + d0);
    float* ob = out + ((size_t)n*D + d0)*T + t;
    #pragma unroll 8
    for (int j = 0; j < 32; ++j) {
        float4 v = crow[j];
        ob[(size_t)(4*j+0)*T] = v.x;
        ob[(size_t)(4*j+1)*T] = v.y;
        ob[(size_t)(4*j+2)*T] = v.z;
        ob[(size_t)(4*j+3)*T] = v.w;
    }
}

// ---------------- finalize: perplexity + commit mean ----------------
__global__ void finalize_kernel(float* __restrict__ out) {
    __shared__ double sbuf[512];
    int t = threadIdx.x;
    float prob = (float)g_hist[t] / 65536.0f;
    sbuf[t] = (double)(prob * logf(prob + 1e-7f));
    __syncthreads();
    for (int s = 256; s > 0; s >>= 1) { if (t < s) sbuf[t] += sbuf[t+s]; __syncthreads(); }
    double psum = sbuf[0];
    __syncthreads();
    sbuf[t] = (t < CTAS) ? (double)g_blockCommit[t] : 0.0;
    __syncthreads();
    for (int s = 256; s > 0; s >>= 1) { if (t < s) sbuf[t] += sbuf[t+s]; __syncthreads(); }
    if (t == 0) {
        out[(size_t)R*D]     = (float)(sbuf[0] / ((double)R * (double)D));
        out[(size_t)R*D + 1] = expf((float)(-psum));
    }
}

// ---------------- launch ----------------
extern "C" void kernel_launch(void* const* d_in, const int* in_sizes, int n_in,
                              void* d_out, int out_size) {
    const float* x        = (const float*)d_in[0];
    const float* codebook = (const float*)d_in[1];
    float* out = (float*)d_out;

    cudaFuncSetAttribute(vq_main, cudaFuncAttributeMaxDynamicSharedMemorySize, SMEM_TOTAL);

    prep_cb<<<NB, D>>>(codebook);
    dim3 tg(T/64, D/64, NBATCH);
    xpose<<<tg, 256>>>(x);
    vq_main<<<CTAS, 256, SMEM_TOTAL>>>(x, codebook);
    dim3 og(R/128, 4);
    out_kernel<<<og, 128>>>(codebook, out);
    finalize_kernel<<<1, 512>>>(out);
}

// round 5
// speedup vs baseline: 2.2860x; 1.2545x over previous
#include <cuda_runtime.h>
#include <cuda_bf16.h>
#include <math.h>
#include <stdint.h>

#define D 512
#define T 2048
#define NBATCH 32
#define NB 512
#define R (NBATCH*T)          // 65536 rows
#define M_TILE 128
#define CTAS (R/M_TILE)       // 512

// -------- scratch (__device__ globals; no allocations allowed) --------
__device__ __align__(16) __nv_bfloat16 g_Xh[(size_t)R*D];   // x bf16, row-major
__device__ __align__(16) __nv_bfloat16 g_Cbh[NB*D];         // codebook bf16 (K-major)
__device__ float g_cnorm[NB];
__device__ float g_sspart[8][R];      // deterministic sumsq partials per d-tile
__device__ int   g_hist[NB];
__device__ int   g_idx[R];
__device__ float g_blockCommit[CTAS];

// -------- helpers --------
__device__ __forceinline__ uint32_t smem_u32(const void* p){
    uint32_t a;
    asm("{ .reg .u64 t; cvta.to.shared.u64 t, %1; cvt.u32.u64 %0, t; }" : "=r"(a) : "l"(p));
    return a;
}
__device__ __forceinline__ void ldsm4(uint32_t (&r)[4], uint32_t addr){
    asm volatile("ldmatrix.sync.aligned.m8n8.x4.shared.b16 {%0,%1,%2,%3}, [%4];"
        : "=r"(r[0]), "=r"(r[1]), "=r"(r[2]), "=r"(r[3]) : "r"(addr));
}
__device__ __forceinline__ void mma_bf16(float (&c)[4], const uint32_t (&a)[4],
                                         uint32_t b0, uint32_t b1){
    asm volatile("mma.sync.aligned.m16n8k16.row.col.f32.bf16.bf16.f32 "
        "{%0,%1,%2,%3}, {%4,%5,%6,%7}, {%8,%9}, {%0,%1,%2,%3};"
        : "+f"(c[0]), "+f"(c[1]), "+f"(c[2]), "+f"(c[3])
        : "r"(a[0]), "r"(a[1]), "r"(a[2]), "r"(a[3]), "r"(b0), "r"(b1));
}
__device__ __forceinline__ void cpasync16(uint32_t dst, const void* src){
    asm volatile("cp.async.cg.shared.global [%0], [%1], 16;" :: "r"(dst), "l"(src) : "memory");
}
#define CP_COMMIT() asm volatile("cp.async.commit_group;" ::: "memory")
#define CP_WAIT1()  asm volatile("cp.async.wait_group 1;" ::: "memory")

// ---------------- prep: codebook -> bf16, cnorm, zero hist ----------------
__global__ void prep_cb(const float* __restrict__ codebook) {
    int c = blockIdx.x, d = threadIdx.x;
    float v = codebook[c*D + d];
    g_Cbh[c*D + d] = __float2bfloat16_rn(v);
    __shared__ float sbuf[D];
    sbuf[d] = v*v;
    __syncthreads();
    for (int s = 256; s > 0; s >>= 1) {
        if (d < s) sbuf[d] += sbuf[d+s];
        __syncthreads();
    }
    if (d == 0) { g_cnorm[c] = sbuf[0]; g_hist[c] = 0; }
}

// ---------------- transpose x -> row-major bf16 + sumsq partials ----------------
__global__ __launch_bounds__(256) void xpose(const float* __restrict__ x) {
    __shared__ float s[64][65];
    int tt = blockIdx.x;
    int dt = blockIdx.y;
    int n  = blockIdx.z;
    int tid = threadIdx.x;
    const float* xp = x + ((size_t)n*D + dt*64)*T + tt*64;
    for (int i = tid; i < 1024; i += 256) {
        int r = i >> 4, q = i & 15;
        float4 v = *reinterpret_cast<const float4*>(xp + (size_t)r*T + q*4);
        s[r][q*4+0] = v.x; s[r][q*4+1] = v.y; s[r][q*4+2] = v.z; s[r][q*4+3] = v.w;
    }
    __syncthreads();
    if (tid < 64) {
        float acc = 0.f;
        #pragma unroll 16
        for (int k = 0; k < 64; ++k) { float v = s[k][tid]; acc = fmaf(v, v, acc); }
        g_sspart[dt][(size_t)n*T + tt*64 + tid] = acc;
    }
    uint32_t* oh = reinterpret_cast<uint32_t*>(g_Xh);
    for (int i = tid; i < 2048; i += 256) {
        int tr = i >> 5, q = i & 31;
        float a = s[2*q][tr], b = s[2*q+1][tr];
        __nv_bfloat16 ah = __float2bfloat16_rn(a), bh = __float2bfloat16_rn(b);
        size_t row = (size_t)n*T + tt*64 + tr;
        size_t base = (row*D + dt*64)/2 + q;
        oh[base] = (uint32_t)__bfloat16_as_ushort(ah) | ((uint32_t)__bfloat16_as_ushort(bh) << 16);
    }
}

// ---------------- main: single-pass bf16 HMMA GEMM + argmin + fp32 rescue ----------------
#define SM_STAGE 4096
#define A_H 0
#define B_H 16384
#define STAGE_SZ 49152        // A 16K + B 32K
#define NSTAGE 3
#define SMEM_TOTAL (SM_STAGE + NSTAGE*STAGE_SZ)   // 151552

__global__ __launch_bounds__(256, 1) void vq_main(const float* __restrict__ x,
                                                  const float* __restrict__ codebook) {
    extern __shared__ char smem[];
    const uint32_t sb = smem_u32(smem);
    float* cn_s  = reinterpret_cast<float*>(smem);
    float* inv_s = reinterpret_cast<float*>(smem + 2048);
    float* sq_s  = reinterpret_cast<float*>(smem + 2560);
    float* cm_s  = reinterpret_cast<float*>(smem + 3072);
    // reduction arrays overlay stage0 (used only after the mainloop)
    float* red_s = reinterpret_cast<float*>(smem + SM_STAGE);
    int*   red_i = reinterpret_cast<int*>(smem + SM_STAGE + 16384);

    const int tid  = threadIdx.x;
    const int lane = tid & 31, wid = tid >> 5;
    const int wm = wid & 1, wn = wid >> 1;
    const int blk  = blockIdx.x;
    const int row0 = blk * M_TILE;

    for (int i = tid; i < NB; i += 256) cn_s[i] = g_cnorm[i];
    if (tid < 128) {
        float sq = 0.f;
        #pragma unroll
        for (int j = 0; j < 8; ++j) sq += g_sspart[j][row0 + tid];
        sq_s[tid]  = sq;
        inv_s[tid] = 1.0f / fmaxf(sqrtf(sq), 1e-12f);
    }
    __syncthreads();

    // stage carries {A, B} bf16 for one K-chunk of 64
    auto prefetch = [&](int kc, int n0, int stg){
        uint32_t base = sb + SM_STAGE + stg*STAGE_SZ;
        #pragma unroll
        for (int t = 0; t < 4; ++t) {          // A: 128 x 64 bf16
            int i = tid + t*256;
            int r = i >> 3, q = i & 7;
            uint32_t off = (uint32_t)(r*128) + (((uint32_t)q*16) ^ (((uint32_t)(r & 7))*16));
            cpasync16(base + A_H + off, g_Xh + (size_t)(row0 + r)*D + kc*64 + q*8);
        }
        #pragma unroll
        for (int t = 0; t < 8; ++t) {          // B: 256 x 64 bf16
            int i = tid + t*256;
            int r = i >> 3, q = i & 7;
            uint32_t off = (uint32_t)(r*128) + (((uint32_t)q*16) ^ (((uint32_t)(r & 7))*16));
            cpasync16(base + B_H + off, g_Cbh + (size_t)(n0 + r)*D + kc*64 + q*8);
        }
    };

    // per-row/slot running top-2 (kept across both N passes)
    float bs1[8], bs2[8]; int bi1[8], bi2[8];
    #pragma unroll
    for (int s = 0; s < 8; ++s) { bs1[s] = 3.4e38f; bs2[s] = 3.4e38f; bi1[s] = 0; bi2[s] = 0; }

    // fragment address bases
    const int rA = wm*64 + (lane & 7) + ((lane >> 3) & 1)*8;
    const uint32_t rowA = (uint32_t)rA * 128;
    const uint32_t kxA  = ((uint32_t)(lane >> 4)) * 16;
    const uint32_t swA  = ((uint32_t)(rA & 7)) * 16;
    const int rBl = (lane & 7) + (lane >> 4)*8;
    const uint32_t kxB  = (((uint32_t)(lane >> 3)) & 1) * 16;
    const uint32_t swB  = ((uint32_t)(lane & 7)) * 16;
    const uint32_t rowB = (uint32_t)(wn*64 + rBl) * 128;

    for (int pass = 0; pass < 2; ++pass) {
        const int n0 = pass * 256;
        float acc[4][8][4];
        #pragma unroll
        for (int a = 0; a < 4; ++a)
            #pragma unroll
            for (int b = 0; b < 8; ++b)
                #pragma unroll
                for (int e = 0; e < 4; ++e) acc[a][b][e] = 0.f;

        __syncthreads();               // stages from previous pass fully consumed
        prefetch(0, n0, 0); CP_COMMIT();
        prefetch(1, n0, 1); CP_COMMIT();

        for (int c = 0; c < 8; ++c) {
            CP_WAIT1();                // stage c complete (c+1 may be in flight)
            __syncthreads();           // + all warps done reading stage (c-1)
            if (c + 2 < 8) prefetch(c + 2, n0, (c + 2) % NSTAGE);
            CP_COMMIT();
            uint32_t ab = sb + SM_STAGE + (c % NSTAGE)*STAGE_SZ;

            #pragma unroll
            for (int ks = 0; ks < 4; ++ks) {
                uint32_t bh[4][4];
                #pragma unroll
                for (int nt2 = 0; nt2 < 4; ++nt2)
                    ldsm4(bh[nt2], ab + B_H + rowB + (uint32_t)nt2*2048 + (((uint32_t)ks*32 + kxB) ^ swB));
                #pragma unroll
                for (int mt = 0; mt < 4; ++mt) {
                    uint32_t aa[4];
                    ldsm4(aa, ab + A_H + rowA + (uint32_t)mt*2048 + (((uint32_t)ks*32 + kxA) ^ swA));
                    #pragma unroll
                    for (int nt2 = 0; nt2 < 4; ++nt2) {
                        mma_bf16(acc[mt][2*nt2],   aa, bh[nt2][0], bh[nt2][1]);
                        mma_bf16(acc[mt][2*nt2+1], aa, bh[nt2][2], bh[nt2][3]);
                    }
                }
            }
        }

        // epilogue: fold this pass's 256 codes into running top-2 per row slot
        #pragma unroll
        for (int mt = 0; mt < 4; ++mt) {
            #pragma unroll
            for (int h = 0; h < 2; ++h) {
                const int slot = mt*2 + h;
                const int row = wm*64 + mt*16 + (lane >> 2) + h*8;
                const float m2inv = -2.0f * inv_s[row];
                #pragma unroll
                for (int nt = 0; nt < 8; ++nt) {
                    int code = n0 + wn*64 + nt*8 + (lane & 3)*2;
                    float s0 = fmaf(m2inv, acc[mt][nt][h*2+0], cn_s[code]);
                    float s1 = fmaf(m2inv, acc[mt][nt][h*2+1], cn_s[code+1]);
                    if (s0 < bs1[slot]) { bs2[slot]=bs1[slot]; bi2[slot]=bi1[slot]; bs1[slot]=s0; bi1[slot]=code; }
                    else if (s0 < bs2[slot]) { bs2[slot]=s0; bi2[slot]=code; }
                    if (s1 < bs1[slot]) { bs2[slot]=bs1[slot]; bi2[slot]=bi1[slot]; bs1[slot]=s1; bi1[slot]=code+1; }
                    else if (s1 < bs2[slot]) { bs2[slot]=s1; bi2[slot]=code+1; }
                }
            }
        }
    }

    // candidate reduction: 16 candidate slices x top-2 per row (overlays stage0)
    __syncthreads();
    #pragma unroll
    for (int mt = 0; mt < 4; ++mt) {
        #pragma unroll
        for (int h = 0; h < 2; ++h) {
            const int slot = mt*2 + h;
            const int row = wm*64 + mt*16 + (lane >> 2) + h*8;
            const int cb = (wn*4 + (lane & 3))*2;
            red_s[row*32 + cb]     = bs1[slot]; red_i[row*32 + cb]     = bi1[slot];
            red_s[row*32 + cb + 1] = bs2[slot]; red_i[row*32 + cb + 1] = bi2[slot];
        }
    }
    __syncthreads();

    if (tid < 128) {
        float s1 = 3.4e38f, s2 = s1, s3 = s1, s4 = s1;
        int i1 = 0, i2 = 0, i3 = 0, i4 = 0;
        for (int c = 0; c < 32; ++c) {
            float s = red_s[tid*32 + c]; int ii = red_i[tid*32 + c];
            if (s < s1 || (s == s1 && ii < i1)) { s4=s3;i4=i3; s3=s2;i3=i2; s2=s1;i2=i1; s1=s;i1=ii; }
            else if (s < s2 || (s == s2 && ii < i2)) { s4=s3;i4=i3; s3=s2;i3=i2; s2=s;i2=ii; }
            else if (s < s3 || (s == s3 && ii < i3)) { s4=s3;i4=i3; s3=s;i3=ii; }
            else if (s < s4 || (s == s4 && ii < i4)) { s4=s;i4=ii; }
        }
        const float inv = inv_s[tid], sq = sq_s[tid];
        float bestS = s1; int bestI = i1;
        if (s2 - s1 < 3e-3f) {   // exact fp32 rescue of top-4 candidates (bf16 err << 3e-3)
            int grow = row0 + tid;
            int nb_ = grow / T, tl = grow % T;
            const float* xr = x + (size_t)nb_*D*T + tl;
            const float* c1p = codebook + (size_t)i1*D;
            const float* c2p = codebook + (size_t)i2*D;
            const float* c3p = codebook + (size_t)i3*D;
            const float* c4p = codebook + (size_t)i4*D;
            float d1 = 0.f, d2 = 0.f, d3 = 0.f, d4 = 0.f;
            for (int d = 0; d < D; ++d) {
                float xv = xr[(size_t)d*T];
                d1 = fmaf(xv, c1p[d], d1); d2 = fmaf(xv, c2p[d], d2);
                d3 = fmaf(xv, c3p[d], d3); d4 = fmaf(xv, c4p[d], d4);
            }
            float e1 = fmaf(-2.0f*inv, d1, cn_s[i1]);
            float e2 = fmaf(-2.0f*inv, d2, cn_s[i2]);
            float e3 = fmaf(-2.0f*inv, d3, cn_s[i3]);
            float e4 = fmaf(-2.0f*inv, d4, cn_s[i4]);
            bestS = e1; bestI = i1;
            if (e2 < bestS || (e2 == bestS && i2 < bestI)) { bestS = e2; bestI = i2; }
            if (e3 < bestS || (e3 == bestS && i3 < bestI)) { bestS = e3; bestI = i3; }
            if (e4 < bestS || (e4 == bestS && i4 < bestI)) { bestS = e4; bestI = i4; }
        }
        g_idx[row0 + tid] = bestI;
        cm_s[tid] = fmaf(sq*inv, inv, bestS);
        atomicAdd(&g_hist[bestI], 1);
    }
    __syncthreads();
    if (tid == 0) {
        float s = 0.f;
        for (int i = 0; i < 128; ++i) s += cm_s[i];
        g_blockCommit[blk] = s;
    }
}

// ---------------- output: direct gather-write, full occupancy ----------------
__global__ __launch_bounds__(128) void out_kernel(const float* __restrict__ codebook,
                                                  float* __restrict__ out) {
    const int rows0 = blockIdx.x * 128;
    const int d0 = blockIdx.y * 128;
    const int row = rows0 + threadIdx.x;
    const int n = row / T;
    const int t = row % T;
    const int code = g_idx[row];
    const float4* crow = reinterpret_cast<const float4*>(codebook + (size_t)code*D + d0);
    float* ob = out + ((size_t)n*D + d0)*T + t;
    #pragma unroll 8
    for (int j = 0; j < 32; ++j) {
        float4 v = crow[j];
        ob[(size_t)(4*j+0)*T] = v.x;
        ob[(size_t)(4*j+1)*T] = v.y;
        ob[(size_t)(4*j+2)*T] = v.z;
        ob[(size_t)(4*j+3)*T] = v.w;
    }
}

// ---------------- finalize: perplexity + commit mean ----------------
__global__ void finalize_kernel(float* __restrict__ out) {
    __shared__ double sbuf[512];
    int t = threadIdx.x;
    float prob = (float)g_hist[t] / 65536.0f;
    sbuf[t] = (double)(prob * logf(prob + 1e-7f));
    __syncthreads();
    for (int s = 256; s > 0; s >>= 1) { if (t < s) sbuf[t] += sbuf[t+s]; __syncthreads(); }
    double psum = sbuf[0];
    __syncthreads();
    sbuf[t] = (t < CTAS) ? (double)g_blockCommit[t] : 0.0;
    __syncthreads();
    for (int s = 256; s > 0; s >>= 1) { if (t < s) sbuf[t] += sbuf[t+s]; __syncthreads(); }
    if (t == 0) {
        out[(size_t)R*D]     = (float)(sbuf[0] / ((double)R * (double)D));
        out[(size_t)R*D + 1] = expf((float)(-psum));
    }
}

// ---------------- launch ----------------
extern "C" void kernel_launch(void* const* d_in, const int* in_sizes, int n_in,
                              void* d_out, int out_size) {
    const float* x        = (const float*)d_in[0];
    const float* codebook = (const float*)d_in[1];
    float* out = (float*)d_out;

    cudaFuncSetAttribute(vq_main, cudaFuncAttributeMaxDynamicSharedMemorySize, SMEM_TOTAL);

    prep_cb<<<NB, D>>>(codebook);
    dim3 tg(T/64, D/64, NBATCH);
    xpose<<<tg, 256>>>(x);
    vq_main<<<CTAS, 256, SMEM_TOTAL>>>(x, codebook);
    dim3 og(R/128, 4);
    out_kernel<<<og, 128>>>(codebook, out);
    finalize_kernel<<<1, 512>>>(out);
}

// round 6
// speedup vs baseline: 2.5011x; 1.0941x over previous
#include <cuda_runtime.h>
#include <cuda_bf16.h>
#include <math.h>
#include <stdint.h>

#define D 512
#define T 2048
#define NBATCH 32
#define NB 512
#define R (NBATCH*T)          // 65536 rows
#define M_TILE 64
#define CTAS (R/M_TILE)       // 1024

// -------- scratch (__device__ globals; no allocations allowed) --------
__device__ __align__(16) __nv_bfloat16 g_Xh[(size_t)R*D];   // x bf16, row-major
__device__ __align__(16) __nv_bfloat16 g_Cbh[NB*D];         // codebook bf16 (K-major)
__device__ float g_cnorm[NB];
__device__ float g_sspart[8][R];      // deterministic sumsq partials per d-tile
__device__ int   g_hist[NB];
__device__ int   g_idx[R];
__device__ float g_blockCommit[CTAS];

// -------- helpers --------
__device__ __forceinline__ uint32_t smem_u32(const void* p){
    uint32_t a;
    asm("{ .reg .u64 t; cvta.to.shared.u64 t, %1; cvt.u32.u64 %0, t; }" : "=r"(a) : "l"(p));
    return a;
}
__device__ __forceinline__ void ldsm4(uint32_t (&r)[4], uint32_t addr){
    asm volatile("ldmatrix.sync.aligned.m8n8.x4.shared.b16 {%0,%1,%2,%3}, [%4];"
        : "=r"(r[0]), "=r"(r[1]), "=r"(r[2]), "=r"(r[3]) : "r"(addr));
}
__device__ __forceinline__ void mma_bf16(float (&c)[4], const uint32_t (&a)[4],
                                         uint32_t b0, uint32_t b1){
    asm volatile("mma.sync.aligned.m16n8k16.row.col.f32.bf16.bf16.f32 "
        "{%0,%1,%2,%3}, {%4,%5,%6,%7}, {%8,%9}, {%0,%1,%2,%3};"
        : "+f"(c[0]), "+f"(c[1]), "+f"(c[2]), "+f"(c[3])
        : "r"(a[0]), "r"(a[1]), "r"(a[2]), "r"(a[3]), "r"(b0), "r"(b1));
}
__device__ __forceinline__ void cpasync16(uint32_t dst, const void* src){
    asm volatile("cp.async.cg.shared.global [%0], [%1], 16;" :: "r"(dst), "l"(src) : "memory");
}
#define CP_COMMIT() asm volatile("cp.async.commit_group;" ::: "memory")
#define CP_WAIT1()  asm volatile("cp.async.wait_group 1;" ::: "memory")

// ---------------- prep: codebook -> bf16, cnorm, zero hist ----------------
__global__ void prep_cb(const float* __restrict__ codebook) {
    int c = blockIdx.x, d = threadIdx.x;
    float v = codebook[c*D + d];
    g_Cbh[c*D + d] = __float2bfloat16_rn(v);
    __shared__ float sbuf[D];
    sbuf[d] = v*v;
    __syncthreads();
    for (int s = 256; s > 0; s >>= 1) {
        if (d < s) sbuf[d] += sbuf[d+s];
        __syncthreads();
    }
    if (d == 0) { g_cnorm[c] = sbuf[0]; g_hist[c] = 0; }
}

// ---------------- transpose x -> row-major bf16 + sumsq partials ----------------
__global__ __launch_bounds__(256) void xpose(const float* __restrict__ x) {
    __shared__ float s[64][65];
    int tt = blockIdx.x;
    int dt = blockIdx.y;
    int n  = blockIdx.z;
    int tid = threadIdx.x;
    const float* xp = x + ((size_t)n*D + dt*64)*T + tt*64;
    for (int i = tid; i < 1024; i += 256) {
        int r = i >> 4, q = i & 15;
        float4 v = *reinterpret_cast<const float4*>(xp + (size_t)r*T + q*4);
        s[r][q*4+0] = v.x; s[r][q*4+1] = v.y; s[r][q*4+2] = v.z; s[r][q*4+3] = v.w;
    }
    __syncthreads();
    if (tid < 64) {
        float acc = 0.f;
        #pragma unroll 16
        for (int k = 0; k < 64; ++k) { float v = s[k][tid]; acc = fmaf(v, v, acc); }
        g_sspart[dt][(size_t)n*T + tt*64 + tid] = acc;
    }
    // coalesced bf16 store: 4 threads per t-row, each packs 16 d -> 32B
    {
        const int tr = tid >> 2;       // 0..63 (t within tile)
        const int part = tid & 3;      // 16 d each
        uint32_t pk[8];
        #pragma unroll
        for (int j = 0; j < 8; ++j) {
            int d0 = part*16 + 2*j;
            __nv_bfloat16 a = __float2bfloat16_rn(s[d0][tr]);
            __nv_bfloat16 b = __float2bfloat16_rn(s[d0+1][tr]);
            pk[j] = (uint32_t)__bfloat16_as_ushort(a) | ((uint32_t)__bfloat16_as_ushort(b) << 16);
        }
        size_t row = (size_t)n*T + tt*64 + tr;
        uint4* dst = reinterpret_cast<uint4*>(
            reinterpret_cast<uint32_t*>(g_Xh) + (row*D + dt*64)/2 + part*8);
        dst[0] = make_uint4(pk[0], pk[1], pk[2], pk[3]);
        dst[1] = make_uint4(pk[4], pk[5], pk[6], pk[7]);
    }
}

// ---------------- main: single-pass bf16 HMMA GEMM + argmin + fp32 rescue ----------------
#define SM_STAGE 4096
#define A_H 0
#define B_H 8192
#define STAGE_SZ 40960        // A 8K + B 32K
#define SMEM_TOTAL (SM_STAGE + 2*STAGE_SZ)   // 86016

__global__ __launch_bounds__(256, 2) void vq_main(const float* __restrict__ x,
                                                  const float* __restrict__ codebook) {
    extern __shared__ char smem[];
    const uint32_t sb = smem_u32(smem);
    float* cn_s  = reinterpret_cast<float*>(smem);          // 512 f
    float* inv_s = reinterpret_cast<float*>(smem + 2048);   // 64 f
    float* sq_s  = reinterpret_cast<float*>(smem + 2304);   // 64 f
    float* cm_s  = reinterpret_cast<float*>(smem + 2560);   // 64 f
    // reduction arrays overlay stage0 (used only after the mainloop)
    float* red_s = reinterpret_cast<float*>(smem + SM_STAGE);          // 64*32 f
    int*   red_i = reinterpret_cast<int*>(smem + SM_STAGE + 8192);     // 64*32 i

    const int tid  = threadIdx.x;
    const int lane = tid & 31, wid = tid >> 5;
    const int wm = wid & 1, wn = wid >> 1;
    const int blk  = blockIdx.x;
    const int row0 = blk * M_TILE;

    for (int i = tid; i < NB; i += 256) cn_s[i] = g_cnorm[i];
    if (tid < M_TILE) {
        float sq = 0.f;
        #pragma unroll
        for (int j = 0; j < 8; ++j) sq += g_sspart[j][row0 + tid];
        sq_s[tid]  = sq;
        inv_s[tid] = 1.0f / fmaxf(sqrtf(sq), 1e-12f);
    }

    // stage carries {A 64x64, B 256x64} bf16 for one K-chunk of 64
    auto prefetch = [&](int kc, int n0, int stg){
        uint32_t base = sb + SM_STAGE + stg*STAGE_SZ;
        #pragma unroll
        for (int t = 0; t < 2; ++t) {          // A: 64 x 64 bf16
            int i = tid + t*256;
            int r = i >> 3, q = i & 7;
            uint32_t off = (uint32_t)(r*128) + (((uint32_t)q*16) ^ (((uint32_t)(r & 7))*16));
            cpasync16(base + A_H + off, g_Xh + (size_t)(row0 + r)*D + kc*64 + q*8);
        }
        #pragma unroll
        for (int t = 0; t < 8; ++t) {          // B: 256 x 64 bf16
            int i = tid + t*256;
            int r = i >> 3, q = i & 7;
            uint32_t off = (uint32_t)(r*128) + (((uint32_t)q*16) ^ (((uint32_t)(r & 7))*16));
            cpasync16(base + B_H + off, g_Cbh + (size_t)(n0 + r)*D + kc*64 + q*8);
        }
    };

    // per-row/slot running top-2 (kept across both N passes)
    float bs1[4], bs2[4]; int bi1[4], bi2[4];
    #pragma unroll
    for (int s = 0; s < 4; ++s) { bs1[s] = 3.4e38f; bs2[s] = 3.4e38f; bi1[s] = 0; bi2[s] = 0; }

    // fragment address bases
    const int rA = wm*32 + (lane & 7) + ((lane >> 3) & 1)*8;
    const uint32_t rowA = (uint32_t)rA * 128;
    const uint32_t kxA  = ((uint32_t)(lane >> 4)) * 16;
    const uint32_t swA  = ((uint32_t)(rA & 7)) * 16;
    const int rBl = (lane & 7) + (lane >> 4)*8;
    const uint32_t kxB  = (((uint32_t)(lane >> 3)) & 1) * 16;
    const uint32_t swB  = ((uint32_t)(lane & 7)) * 16;
    const uint32_t rowB = (uint32_t)(wn*64 + rBl) * 128;

    __syncthreads();

    for (int pass = 0; pass < 2; ++pass) {
        const int n0 = pass * 256;
        float acc[2][8][4];
        #pragma unroll
        for (int a = 0; a < 2; ++a)
            #pragma unroll
            for (int b = 0; b < 8; ++b)
                #pragma unroll
                for (int e = 0; e < 4; ++e) acc[a][b][e] = 0.f;

        prefetch(0, n0, 0); CP_COMMIT();
        prefetch(1, n0, 1); CP_COMMIT();

        for (int c = 0; c < 8; ++c) {
            CP_WAIT1();                // stage c complete
            __syncthreads();
            uint32_t ab = sb + SM_STAGE + (c & 1)*STAGE_SZ;

            #pragma unroll
            for (int ks = 0; ks < 4; ++ks) {
                uint32_t bh[4][4];
                #pragma unroll
                for (int nt2 = 0; nt2 < 4; ++nt2)
                    ldsm4(bh[nt2], ab + B_H + rowB + (uint32_t)nt2*2048 + (((uint32_t)ks*32 + kxB) ^ swB));
                #pragma unroll
                for (int mt = 0; mt < 2; ++mt) {
                    uint32_t aa[4];
                    ldsm4(aa, ab + A_H + rowA + (uint32_t)mt*2048 + (((uint32_t)ks*32 + kxA) ^ swA));
                    #pragma unroll
                    for (int nt2 = 0; nt2 < 4; ++nt2) {
                        mma_bf16(acc[mt][2*nt2],   aa, bh[nt2][0], bh[nt2][1]);
                        mma_bf16(acc[mt][2*nt2+1], aa, bh[nt2][2], bh[nt2][3]);
                    }
                }
            }
            __syncthreads();           // all warps done reading stage c before overwrite
            if (c + 2 < 8) prefetch(c + 2, n0, (c + 2) & 1);
            CP_COMMIT();
        }

        // epilogue: fold this pass's 256 codes into running top-2 per row slot
        #pragma unroll
        for (int mt = 0; mt < 2; ++mt) {
            #pragma unroll
            for (int h = 0; h < 2; ++h) {
                const int slot = mt*2 + h;
                const int row = wm*32 + mt*16 + (lane >> 2) + h*8;
                const float m2inv = -2.0f * inv_s[row];
                #pragma unroll
                for (int nt = 0; nt < 8; ++nt) {
                    int code = n0 + wn*64 + nt*8 + (lane & 3)*2;
                    float s0 = fmaf(m2inv, acc[mt][nt][h*2+0], cn_s[code]);
                    float s1 = fmaf(m2inv, acc[mt][nt][h*2+1], cn_s[code+1]);
                    if (s0 < bs1[slot]) { bs2[slot]=bs1[slot]; bi2[slot]=bi1[slot]; bs1[slot]=s0; bi1[slot]=code; }
                    else if (s0 < bs2[slot]) { bs2[slot]=s0; bi2[slot]=code; }
                    if (s1 < bs1[slot]) { bs2[slot]=bs1[slot]; bi2[slot]=bi1[slot]; bs1[slot]=s1; bi1[slot]=code+1; }
                    else if (s1 < bs2[slot]) { bs2[slot]=s1; bi2[slot]=code+1; }
                }
            }
        }
    }

    // candidate reduction: 16 candidate slices x top-2 per row (overlays stage0)
    __syncthreads();
    #pragma unroll
    for (int mt = 0; mt < 2; ++mt) {
        #pragma unroll
        for (int h = 0; h < 2; ++h) {
            const int slot = mt*2 + h;
            const int row = wm*32 + mt*16 + (lane >> 2) + h*8;
            const int cb = (wn*4 + (lane & 3))*2;
            red_s[row*32 + cb]     = bs1[slot]; red_i[row*32 + cb]     = bi1[slot];
            red_s[row*32 + cb + 1] = bs2[slot]; red_i[row*32 + cb + 1] = bi2[slot];
        }
    }
    __syncthreads();

    if (tid < M_TILE) {
        float s1 = 3.4e38f, s2 = s1, s3 = s1, s4 = s1;
        int i1 = 0, i2 = 0, i3 = 0, i4 = 0;
        for (int c = 0; c < 32; ++c) {
            float s = red_s[tid*32 + c]; int ii = red_i[tid*32 + c];
            if (s < s1 || (s == s1 && ii < i1)) { s4=s3;i4=i3; s3=s2;i3=i2; s2=s1;i2=i1; s1=s;i1=ii; }
            else if (s < s2 || (s == s2 && ii < i2)) { s4=s3;i4=i3; s3=s2;i3=i2; s2=s;i2=ii; }
            else if (s < s3 || (s == s3 && ii < i3)) { s4=s3;i4=i3; s3=s;i3=ii; }
            else if (s < s4 || (s == s4 && ii < i4)) { s4=s;i4=ii; }
        }
        const float inv = inv_s[tid], sq = sq_s[tid];
        float bestS = s1; int bestI = i1;
        if (s2 - s1 < 3e-3f) {   // exact fp32 rescue of top-4 candidates (bf16 err << 3e-3)
            int grow = row0 + tid;
            int nb_ = grow / T, tl = grow % T;
            const float* xr = x + (size_t)nb_*D*T + tl;
            const float* c1p = codebook + (size_t)i1*D;
            const float* c2p = codebook + (size_t)i2*D;
            const float* c3p = codebook + (size_t)i3*D;
            const float* c4p = codebook + (size_t)i4*D;
            float d1 = 0.f, d2 = 0.f, d3 = 0.f, d4 = 0.f;
            for (int d = 0; d < D; ++d) {
                float xv = xr[(size_t)d*T];
                d1 = fmaf(xv, c1p[d], d1); d2 = fmaf(xv, c2p[d], d2);
                d3 = fmaf(xv, c3p[d], d3); d4 = fmaf(xv, c4p[d], d4);
            }
            float e1 = fmaf(-2.0f*inv, d1, cn_s[i1]);
            float e2 = fmaf(-2.0f*inv, d2, cn_s[i2]);
            float e3 = fmaf(-2.0f*inv, d3, cn_s[i3]);
            float e4 = fmaf(-2.0f*inv, d4, cn_s[i4]);
            bestS = e1; bestI = i1;
            if (e2 < bestS || (e2 == bestS && i2 < bestI)) { bestS = e2; bestI = i2; }
            if (e3 < bestS || (e3 == bestS && i3 < bestI)) { bestS = e3; bestI = i3; }
            if (e4 < bestS || (e4 == bestS && i4 < bestI)) { bestS = e4; bestI = i4; }
        }
        g_idx[row0 + tid] = bestI;
        cm_s[tid] = fmaf(sq*inv, inv, bestS);
        atomicAdd(&g_hist[bestI], 1);
    }
    __syncthreads();
    if (tid == 0) {
        float s = 0.f;
        for (int i = 0; i < M_TILE; ++i) s += cm_s[i];
        g_blockCommit[blk] = s;
    }
}

// ---------------- output: direct gather-write ----------------
__global__ __launch_bounds__(128) void out_kernel(const float* __restrict__ codebook,
                                                  float* __restrict__ out) {
    const int rows0 = blockIdx.x * 128;
    const int d0 = blockIdx.y * 64;
    const int row = rows0 + threadIdx.x;
    const int n = row / T;
    const int t = row % T;
    const int code = g_idx[row];
    const float4* crow = reinterpret_cast<const float4*>(codebook + (size_t)code*D + d0);
    float* ob = out + ((size_t)n*D + d0)*T + t;
    #pragma unroll 16
    for (int j = 0; j < 16; ++j) {
        float4 v = crow[j];
        ob[(size_t)(4*j+0)*T] = v.x;
        ob[(size_t)(4*j+1)*T] = v.y;
        ob[(size_t)(4*j+2)*T] = v.z;
        ob[(size_t)(4*j+3)*T] = v.w;
    }
}

// ---------------- finalize: perplexity + commit mean ----------------
__global__ void finalize_kernel(float* __restrict__ out) {
    __shared__ double sbuf[512];
    int t = threadIdx.x;
    float prob = (float)g_hist[t] / 65536.0f;
    sbuf[t] = (double)(prob * logf(prob + 1e-7f));
    __syncthreads();
    for (int s = 256; s > 0; s >>= 1) { if (t < s) sbuf[t] += sbuf[t+s]; __syncthreads(); }
    double psum = sbuf[0];
    __syncthreads();
    double c = 0.0;
    for (int i = t; i < CTAS; i += 512) c += (double)g_blockCommit[i];
    sbuf[t] = c;
    __syncthreads();
    for (int s = 256; s > 0; s >>= 1) { if (t < s) sbuf[t] += sbuf[t+s]; __syncthreads(); }
    if (t == 0) {
        out[(size_t)R*D]     = (float)(sbuf[0] / ((double)R * (double)D));
        out[(size_t)R*D + 1] = expf((float)(-psum));
    }
}

// ---------------- launch ----------------
extern "C" void kernel_launch(void* const* d_in, const int* in_sizes, int n_in,
                              void* d_out, int out_size) {
    const float* x        = (const float*)d_in[0];
    const float* codebook = (const float*)d_in[1];
    float* out = (float*)d_out;

    cudaFuncSetAttribute(vq_main, cudaFuncAttributeMaxDynamicSharedMemorySize, SMEM_TOTAL);

    prep_cb<<<NB, D>>>(codebook);
    dim3 tg(T/64, D/64, NBATCH);
    xpose<<<tg, 256>>>(x);
    vq_main<<<CTAS, 256, SMEM_TOTAL>>>(x, codebook);
    dim3 og(R/128, 8);
    out_kernel<<<og, 128>>>(codebook, out);
    finalize_kernel<<<1, 512>>>(out);
}

// round 8
// speedup vs baseline: 3.2520x; 1.3002x over previous
#include <cuda_runtime.h>
#include <cuda_bf16.h>
#include <math.h>
#include <stdint.h>

#define D 512
#define T 2048
#define NBATCH 32
#define NB 512
#define R (NBATCH*T)          // 65536 rows
#define M_TILE 64
#define CTAS (R/M_TILE)       // 1024

// -------- scratch (__device__ globals; no allocations allowed) --------
__device__ __align__(16) __nv_bfloat16 g_Cbh[NB*D];         // codebook bf16 (K-major)
__device__ float g_cnorm[NB];
__device__ int   g_hist[NB];
__device__ float g_blockCommit[CTAS];

// -------- helpers --------
__device__ __forceinline__ uint32_t smem_u32(const void* p){
    uint32_t a;
    asm("{ .reg .u64 t; cvta.to.shared.u64 t, %1; cvt.u32.u64 %0, t; }" : "=r"(a) : "l"(p));
    return a;
}
__device__ __forceinline__ void ldsm4(uint32_t (&r)[4], uint32_t addr){
    asm volatile("ldmatrix.sync.aligned.m8n8.x4.shared.b16 {%0,%1,%2,%3}, [%4];"
        : "=r"(r[0]), "=r"(r[1]), "=r"(r[2]), "=r"(r[3]) : "r"(addr));
}
__device__ __forceinline__ void mma_bf16(float (&c)[4], const uint32_t (&a)[4],
                                         uint32_t b0, uint32_t b1){
    asm volatile("mma.sync.aligned.m16n8k16.row.col.f32.bf16.bf16.f32 "
        "{%0,%1,%2,%3}, {%4,%5,%6,%7}, {%8,%9}, {%0,%1,%2,%3};"
        : "+f"(c[0]), "+f"(c[1]), "+f"(c[2]), "+f"(c[3])
        : "r"(a[0]), "r"(a[1]), "r"(a[2]), "r"(a[3]), "r"(b0), "r"(b1));
}
__device__ __forceinline__ void cpasync16(uint32_t dst, const void* src){
    asm volatile("cp.async.cg.shared.global [%0], [%1], 16;" :: "r"(dst), "l"(src) : "memory");
}
#define CP_COMMIT() asm volatile("cp.async.commit_group;" ::: "memory")
#define CP_WAIT1()  asm volatile("cp.async.wait_group 1;" ::: "memory")

// ---------------- prep: codebook -> bf16, cnorm, zero hist ----------------
__global__ void prep_cb(const float* __restrict__ codebook) {
    int c = blockIdx.x, d = threadIdx.x;
    float v = codebook[c*D + d];
    g_Cbh[c*D + d] = __float2bfloat16_rn(v);
    __shared__ float sbuf[D];
    sbuf[d] = v*v;
    __syncthreads();
    for (int s = 256; s > 0; s >>= 1) {
        if (d < s) sbuf[d] += sbuf[d+s];
        __syncthreads();
    }
    if (d == 0) { g_cnorm[c] = sbuf[0]; g_hist[c] = 0; }
}

// ---------------- fused main: transpose-in + GEMM/argmin + rescue + output ----------------
// smem layout
#define SM_CN    0
#define SM_INV   2048
#define SM_SQ    2304
#define SM_CM    2560
#define SM_IDX   2816
#define SM_PART  3072      // 4 x 64 partial sumsq
#define SM_AFULL 4096      // 64 KB: 8 chunks x [64m][64k] bf16 swizzled
#define SM_BST   (4096 + 65536)
#define B_STAGE  16384     // 128 codes x 64k bf16
#define SMEM_TOTAL (SM_BST + 2*B_STAGE)   // 102400

__global__ __launch_bounds__(256, 2) void vq_main(const float* __restrict__ x,
                                                  const float* __restrict__ codebook,
                                                  float* __restrict__ out) {
    extern __shared__ char smem[];
    const uint32_t sb = smem_u32(smem);
    float* cn_s  = reinterpret_cast<float*>(smem + SM_CN);
    float* inv_s = reinterpret_cast<float*>(smem + SM_INV);
    float* sq_s  = reinterpret_cast<float*>(smem + SM_SQ);
    float* cm_s  = reinterpret_cast<float*>(smem + SM_CM);
    int*   idx_s = reinterpret_cast<int*>(smem + SM_IDX);
    float* part_s= reinterpret_cast<float*>(smem + SM_PART);
    float* red_s = reinterpret_cast<float*>(smem + SM_BST);          // overlays B stages post-loop
    int*   red_i = reinterpret_cast<int*>(smem + SM_BST + 8192);

    const int tid  = threadIdx.x;
    const int lane = tid & 31, wid = tid >> 5;
    const int wm = wid & 1, wn = wid >> 1;
    const int blk  = blockIdx.x;
    const int row0 = blk * M_TILE;
    const int n    = row0 / T;
    const int t0   = row0 % T;

    for (int i = tid; i < NB; i += 256) cn_s[i] = g_cnorm[i];

    // B chunk prefetch: 128 codes x 64 k bf16 (16KB) into stage stg
    auto prefetchB = [&](int c, int stg){
        const int kc = c & 7;
        const int n0 = (c >> 3) * 128;
        uint32_t base = sb + SM_BST + stg*B_STAGE;
        #pragma unroll
        for (int t2 = 0; t2 < 4; ++t2) {
            int i = tid + t2*256;
            int r = i >> 3, q = i & 7;
            uint32_t off = (uint32_t)(r*128) + (((uint32_t)q*16) ^ (((uint32_t)(r & 7))*16));
            cpasync16(base + off, g_Cbh + (size_t)(n0 + r)*D + kc*64 + q*8);
        }
    };

    prefetchB(0, 0); CP_COMMIT();
    prefetchB(1, 1); CP_COMMIT();

    // ---- A prologue: LDG x slice, convert bf16, store swizzled A-full; sumsq ----
    {
        const int m  = tid >> 2;   // row within tile (t-index)
        const int sg = tid & 3;    // k-subgroup of 16
        float ss = 0.f;
        for (int kc = 0; kc < 8; ++kc) {
            const float* xc = x + ((size_t)n*D + kc*64 + 16*sg)*T + t0 + m;
            float v[16];
            #pragma unroll
            for (int j = 0; j < 16; ++j) v[j] = xc[(size_t)j*T];
            #pragma unroll
            for (int j = 0; j < 16; ++j) ss = fmaf(v[j], v[j], ss);
            uint32_t pk[8];
            #pragma unroll
            for (int jp = 0; jp < 8; ++jp) {
                __nv_bfloat16 a = __float2bfloat16_rn(v[2*jp]);
                __nv_bfloat16 b = __float2bfloat16_rn(v[2*jp+1]);
                pk[jp] = (uint32_t)__bfloat16_as_ushort(a) | ((uint32_t)__bfloat16_as_ushort(b) << 16);
            }
            char* arow = smem + SM_AFULL + kc*8192 + m*128;
            int seg0 = (2*sg) ^ (m & 7);
            int seg1 = (2*sg+1) ^ (m & 7);
            *reinterpret_cast<uint4*>(arow + seg0*16) = make_uint4(pk[0], pk[1], pk[2], pk[3]);
            *reinterpret_cast<uint4*>(arow + seg1*16) = make_uint4(pk[4], pk[5], pk[6], pk[7]);
        }
        part_s[sg*64 + m] = ss;
    }
    __syncthreads();
    if (tid < M_TILE) {   // fixed-order combine -> deterministic
        float sq = part_s[tid] + part_s[64+tid] + part_s[128+tid] + part_s[192+tid];
        sq_s[tid]  = sq;
        inv_s[tid] = 1.0f / fmaxf(sqrtf(sq), 1e-12f);
    }

    // per-row/slot running top-2 across all 4 passes
    float bs1[4], bs2[4]; int bi1[4], bi2[4];
    #pragma unroll
    for (int s = 0; s < 4; ++s) { bs1[s] = 3.4e38f; bs2[s] = 3.4e38f; bi1[s] = 0; bi2[s] = 0; }

    float acc[2][4][4];
    #pragma unroll
    for (int a = 0; a < 2; ++a)
        #pragma unroll
        for (int b = 0; b < 4; ++b)
            #pragma unroll
            for (int e = 0; e < 4; ++e) acc[a][b][e] = 0.f;

    // fragment address bases
    const int rA = wm*32 + (lane & 7) + ((lane >> 3) & 1)*8;
    const uint32_t rowA = (uint32_t)rA * 128;
    const uint32_t kxA  = ((uint32_t)(lane >> 4)) * 16;
    const uint32_t swA  = ((uint32_t)(rA & 7)) * 16;
    const int rBl = (lane & 7) + (lane >> 4)*8;
    const uint32_t kxB  = (((uint32_t)(lane >> 3)) & 1) * 16;
    const uint32_t swB  = ((uint32_t)(lane & 7)) * 16;
    const uint32_t rowB = (uint32_t)(wn*32 + rBl) * 128;

    // ---- mainloop: 4 passes x 8 k-chunks, B double-buffered (wait THEN sync) ----
    for (int c = 0; c < 32; ++c) {
        const int kc = c & 7;
        CP_WAIT1();                    // my group c complete (group c+1 may be pending)
        __syncthreads();               // ALL threads' group c complete -> stage c&1 readable
        uint32_t bb = sb + SM_BST + (c & 1)*B_STAGE;
        uint32_t aBase = sb + SM_AFULL + kc*8192;

        #pragma unroll
        for (int ks = 0; ks < 4; ++ks) {
            uint32_t bh[2][4];
            #pragma unroll
            for (int nt2 = 0; nt2 < 2; ++nt2)
                ldsm4(bh[nt2], bb + rowB + (uint32_t)nt2*2048 + (((uint32_t)ks*32 + kxB) ^ swB));
            #pragma unroll
            for (int mt = 0; mt < 2; ++mt) {
                uint32_t aa[4];
                ldsm4(aa, aBase + rowA + (uint32_t)mt*2048 + (((uint32_t)ks*32 + kxA) ^ swA));
                #pragma unroll
                for (int nt2 = 0; nt2 < 2; ++nt2) {
                    mma_bf16(acc[mt][2*nt2],   aa, bh[nt2][0], bh[nt2][1]);
                    mma_bf16(acc[mt][2*nt2+1], aa, bh[nt2][2], bh[nt2][3]);
                }
            }
        }

        if (kc == 7) {   // end of pass: fold 128 codes into running top-2, reset acc
            const int n0 = (c >> 3) * 128;
            #pragma unroll
            for (int mt = 0; mt < 2; ++mt) {
                #pragma unroll
                for (int h = 0; h < 2; ++h) {
                    const int slot = mt*2 + h;
                    const int row = wm*32 + mt*16 + (lane >> 2) + h*8;
                    const float m2inv = -2.0f * inv_s[row];
                    #pragma unroll
                    for (int nt = 0; nt < 4; ++nt) {
                        int code = n0 + wn*32 + nt*8 + (lane & 3)*2;
                        float s0 = fmaf(m2inv, acc[mt][nt][h*2+0], cn_s[code]);
                        float s1 = fmaf(m2inv, acc[mt][nt][h*2+1], cn_s[code+1]);
                        if (s0 < bs1[slot]) { bs2[slot]=bs1[slot]; bi2[slot]=bi1[slot]; bs1[slot]=s0; bi1[slot]=code; }
                        else if (s0 < bs2[slot]) { bs2[slot]=s0; bi2[slot]=code; }
                        if (s1 < bs1[slot]) { bs2[slot]=bs1[slot]; bi2[slot]=bi1[slot]; bs1[slot]=s1; bi1[slot]=code+1; }
                        else if (s1 < bs2[slot]) { bs2[slot]=s1; bi2[slot]=code+1; }
                    }
                }
            }
            #pragma unroll
            for (int a = 0; a < 2; ++a)
                #pragma unroll
                for (int b = 0; b < 4; ++b)
                    #pragma unroll
                    for (int e = 0; e < 4; ++e) acc[a][b][e] = 0.f;
        }

        __syncthreads();               // all readers of stage c&1 done before overwrite
        if (c + 2 < 32) { prefetchB(c + 2, c & 1); }
        CP_COMMIT();                   // empty group ok on final iters
    }

    // ---- candidate reduction (overlays B stages) ----
    __syncthreads();
    #pragma unroll
    for (int mt = 0; mt < 2; ++mt) {
        #pragma unroll
        for (int h = 0; h < 2; ++h) {
            const int slot = mt*2 + h;
            const int row = wm*32 + mt*16 + (lane >> 2) + h*8;
            const int cb = (wn*4 + (lane & 3))*2;
            red_s[row*32 + cb]     = bs1[slot]; red_i[row*32 + cb]     = bi1[slot];
            red_s[row*32 + cb + 1] = bs2[slot]; red_i[row*32 + cb + 1] = bi2[slot];
        }
    }
    __syncthreads();

    if (tid < M_TILE) {
        float s1 = 3.4e38f, s2 = s1, s3 = s1, s4 = s1;
        int i1 = 0, i2 = 0, i3 = 0, i4 = 0;
        for (int c = 0; c < 32; ++c) {
            float s = red_s[tid*32 + c]; int ii = red_i[tid*32 + c];
            if (s < s1 || (s == s1 && ii < i1)) { s4=s3;i4=i3; s3=s2;i3=i2; s2=s1;i2=i1; s1=s;i1=ii; }
            else if (s < s2 || (s == s2 && ii < i2)) { s4=s3;i4=i3; s3=s2;i3=i2; s2=s;i2=ii; }
            else if (s < s3 || (s == s3 && ii < i3)) { s4=s3;i4=i3; s3=s;i3=ii; }
            else if (s < s4 || (s == s4 && ii < i4)) { s4=s;i4=ii; }
        }
        const float inv = inv_s[tid], sq = sq_s[tid];
        float bestS = s1; int bestI = i1;
        if (s2 - s1 < 3e-3f) {   // exact fp32 rescue of top-4 candidates
            const float* xr = x + (size_t)n*D*T + t0 + tid;
            const float* c1p = codebook + (size_t)i1*D;
            const float* c2p = codebook + (size_t)i2*D;
            const float* c3p = codebook + (size_t)i3*D;
            const float* c4p = codebook + (size_t)i4*D;
            float d1 = 0.f, d2 = 0.f, d3 = 0.f, d4 = 0.f;
            for (int d = 0; d < D; ++d) {
                float xv = xr[(size_t)d*T];
                d1 = fmaf(xv, c1p[d], d1); d2 = fmaf(xv, c2p[d], d2);
                d3 = fmaf(xv, c3p[d], d3); d4 = fmaf(xv, c4p[d], d4);
            }
            float e1 = fmaf(-2.0f*inv, d1, cn_s[i1]);
            float e2 = fmaf(-2.0f*inv, d2, cn_s[i2]);
            float e3 = fmaf(-2.0f*inv, d3, cn_s[i3]);
            float e4 = fmaf(-2.0f*inv, d4, cn_s[i4]);
            bestS = e1; bestI = i1;
            if (e2 < bestS || (e2 == bestS && i2 < bestI)) { bestS = e2; bestI = i2; }
            if (e3 < bestS || (e3 == bestS && i3 < bestI)) { bestS = e3; bestI = i3; }
            if (e4 < bestS || (e4 == bestS && i4 < bestI)) { bestS = e4; bestI = i4; }
        }
        idx_s[tid] = bestI;
        cm_s[tid] = fmaf(sq*inv, inv, bestS);
        atomicAdd(&g_hist[bestI], 1);
    }
    __syncthreads();
    if (tid == 0) {
        float s = 0.f;
        for (int i = 0; i < M_TILE; ++i) s += cm_s[i];
        g_blockCommit[blk] = s;
    }

    // ---- fused output: gather + register transpose + coalesced write ----
    {
        const int mq = tid & 15;      // t-quad: t = t0 + 4*mq + i
        const int dg = tid >> 4;      // d-group of 4
        int r0i = idx_s[4*mq + 0], r1i = idx_s[4*mq + 1];
        int r2i = idx_s[4*mq + 2], r3i = idx_s[4*mq + 3];
        #pragma unroll
        for (int dt = 0; dt < 8; ++dt) {
            const int d0 = dt*64 + dg*4;
            float4 a = *reinterpret_cast<const float4*>(codebook + (size_t)r0i*D + d0);
            float4 b = *reinterpret_cast<const float4*>(codebook + (size_t)r1i*D + d0);
            float4 cc = *reinterpret_cast<const float4*>(codebook + (size_t)r2i*D + d0);
            float4 dd = *reinterpret_cast<const float4*>(codebook + (size_t)r3i*D + d0);
            float* ob = out + ((size_t)n*D + d0)*T + t0 + 4*mq;
            *reinterpret_cast<float4*>(ob)              = make_float4(a.x, b.x, cc.x, dd.x);
            *reinterpret_cast<float4*>(ob + T)          = make_float4(a.y, b.y, cc.y, dd.y);
            *reinterpret_cast<float4*>(ob + 2*(size_t)T)= make_float4(a.z, b.z, cc.z, dd.z);
            *reinterpret_cast<float4*>(ob + 3*(size_t)T)= make_float4(a.w, b.w, cc.w, dd.w);
        }
    }
}

// ---------------- finalize: perplexity + commit mean ----------------
__global__ void finalize_kernel(float* __restrict__ out) {
    __shared__ double sbuf[512];
    int t = threadIdx.x;
    float prob = (float)g_hist[t] / 65536.0f;
    sbuf[t] = (double)(prob * logf(prob + 1e-7f));
    __syncthreads();
    for (int s = 256; s > 0; s >>= 1) { if (t < s) sbuf[t] += sbuf[t+s]; __syncthreads(); }
    double psum = sbuf[0];
    __syncthreads();
    double c = 0.0;
    for (int i = t; i < CTAS; i += 512) c += (double)g_blockCommit[i];
    sbuf[t] = c;
    __syncthreads();
    for (int s = 256; s > 0; s >>= 1) { if (t < s) sbuf[t] += sbuf[t+s]; __syncthreads(); }
    if (t == 0) {
        out[(size_t)R*D]     = (float)(sbuf[0] / ((double)R * (double)D));
        out[(size_t)R*D + 1] = expf((float)(-psum));
    }
}

// ---------------- launch ----------------
extern "C" void kernel_launch(void* const* d_in, const int* in_sizes, int n_in,
                              void* d_out, int out_size) {
    const float* x        = (const float*)d_in[0];
    const float* codebook = (const float*)d_in[1];
    float* out = (float*)d_out;

    cudaFuncSetAttribute(vq_main, cudaFuncAttributeMaxDynamicSharedMemorySize, SMEM_TOTAL);

    prep_cb<<<NB, D>>>(codebook);
    vq_main<<<CTAS, 256, SMEM_TOTAL>>>(x, codebook, out);
    finalize_kernel<<<1, 512>>>(out);
}

// round 9
// speedup vs baseline: 3.5522x; 1.0923x over previous
#include <cuda_runtime.h>
#include <cuda_bf16.h>
#include <math.h>
#include <stdint.h>

#define D 512
#define T 2048
#define NBATCH 32
#define NB 512
#define R (NBATCH*T)          // 65536 rows
#define M_TILE 64
#define CTAS (R/M_TILE)       // 1024

// -------- scratch (__device__ globals; no allocations allowed) --------
__device__ __align__(16) __nv_bfloat16 g_Cbh[NB*D];         // codebook bf16 (K-major)
__device__ float g_cnorm[NB];
__device__ int   g_hist[NB];
__device__ float g_blockCommit[CTAS];

// -------- helpers --------
__device__ __forceinline__ uint32_t smem_u32(const void* p){
    uint32_t a;
    asm("{ .reg .u64 t; cvta.to.shared.u64 t, %1; cvt.u32.u64 %0, t; }" : "=r"(a) : "l"(p));
    return a;
}
__device__ __forceinline__ void ldsm4(uint32_t (&r)[4], uint32_t addr){
    asm volatile("ldmatrix.sync.aligned.m8n8.x4.shared.b16 {%0,%1,%2,%3}, [%4];"
        : "=r"(r[0]), "=r"(r[1]), "=r"(r[2]), "=r"(r[3]) : "r"(addr));
}
__device__ __forceinline__ void mma_bf16(float (&c)[4], const uint32_t (&a)[4],
                                         uint32_t b0, uint32_t b1){
    asm volatile("mma.sync.aligned.m16n8k16.row.col.f32.bf16.bf16.f32 "
        "{%0,%1,%2,%3}, {%4,%5,%6,%7}, {%8,%9}, {%0,%1,%2,%3};"
        : "+f"(c[0]), "+f"(c[1]), "+f"(c[2]), "+f"(c[3])
        : "r"(a[0]), "r"(a[1]), "r"(a[2]), "r"(a[3]), "r"(b0), "r"(b1));
}
__device__ __forceinline__ void cpasync16(uint32_t dst, const void* src){
    asm volatile("cp.async.cg.shared.global [%0], [%1], 16;" :: "r"(dst), "l"(src) : "memory");
}
#define CP_COMMIT() asm volatile("cp.async.commit_group;" ::: "memory")
#define CP_WAIT1()  asm volatile("cp.async.wait_group 1;" ::: "memory")

// ---------------- prep: codebook -> bf16, cnorm, zero hist ----------------
__global__ void prep_cb(const float* __restrict__ codebook) {
    int c = blockIdx.x, d = threadIdx.x;
    float v = codebook[c*D + d];
    g_Cbh[c*D + d] = __float2bfloat16_rn(v);
    __shared__ float sbuf[D];
    sbuf[d] = v*v;
    __syncthreads();
    for (int s = 256; s > 0; s >>= 1) {
        if (d < s) sbuf[d] += sbuf[d+s];
        __syncthreads();
    }
    if (d == 0) { g_cnorm[c] = sbuf[0]; g_hist[c] = 0; }
}

// ---------------- fused main ----------------
// smem layout
#define SM_CN    0
#define SM_INV   2048
#define SM_SQ    2304
#define SM_CM    2560
#define SM_IDX   2816
#define SM_PART  3072      // 4 x 64 partial sumsq
#define SM_AFULL 4096      // 64 KB: 8 chunks x [64m][64k] bf16 swizzled
#define SM_BST   (4096 + 65536)
#define B_STAGE  16384     // 128 codes x 64k bf16
#define SMEM_TOTAL (SM_BST + 2*B_STAGE)   // 102400
// post-loop overlays (on top of B stages)
#define OV_REDS  SM_BST             // float[64*16]
#define OV_REDI  (SM_BST + 4096)    // int[64*16]
#define OV_IDX4  (SM_BST + 8192)    // int[64*4]
#define OV_FLAG  (SM_BST + 9216)    // int[64]
#define OV_DRES  (SM_BST + 9472)    // float[64*4]
#define OV_PROVS (SM_BST + 10496)   // float[64]
#define OV_PROVI (SM_BST + 10752)   // int[64]

__global__ __launch_bounds__(256, 2) void vq_main(const float* __restrict__ x,
                                                  const float* __restrict__ codebook,
                                                  float* __restrict__ out) {
    extern __shared__ char smem[];
    const uint32_t sb = smem_u32(smem);
    float* cn_s  = reinterpret_cast<float*>(smem + SM_CN);
    float* inv_s = reinterpret_cast<float*>(smem + SM_INV);
    float* sq_s  = reinterpret_cast<float*>(smem + SM_SQ);
    float* cm_s  = reinterpret_cast<float*>(smem + SM_CM);
    int*   idx_s = reinterpret_cast<int*>(smem + SM_IDX);
    float* part_s= reinterpret_cast<float*>(smem + SM_PART);
    float* red_s = reinterpret_cast<float*>(smem + OV_REDS);
    int*   red_i = reinterpret_cast<int*>(smem + OV_REDI);
    int*   idx4_s= reinterpret_cast<int*>(smem + OV_IDX4);
    int*   flag_s= reinterpret_cast<int*>(smem + OV_FLAG);
    float* dres_s= reinterpret_cast<float*>(smem + OV_DRES);
    float* provS = reinterpret_cast<float*>(smem + OV_PROVS);
    int*   provI = reinterpret_cast<int*>(smem + OV_PROVI);

    const int tid  = threadIdx.x;
    const int lane = tid & 31, wid = tid >> 5;
    const int wm = wid & 3, wn = wid >> 2;        // 4 x 2 warp grid, warp tile 16x64
    const int blk  = blockIdx.x;
    const int row0 = blk * M_TILE;
    const int n    = row0 / T;
    const int t0   = row0 % T;

    for (int i = tid; i < NB; i += 256) cn_s[i] = g_cnorm[i];

    // B chunk prefetch: 128 codes x 64 k bf16 (16KB) into stage stg
    auto prefetchB = [&](int c, int stg){
        const int kc = c & 7;
        const int n0 = (c >> 3) * 128;
        uint32_t base = sb + SM_BST + stg*B_STAGE;
        #pragma unroll
        for (int t2 = 0; t2 < 4; ++t2) {
            int i = tid + t2*256;
            int r = i >> 3, q = i & 7;
            uint32_t off = (uint32_t)(r*128) + (((uint32_t)q*16) ^ (((uint32_t)(r & 7))*16));
            cpasync16(base + off, g_Cbh + (size_t)(n0 + r)*D + kc*64 + q*8);
        }
    };

    prefetchB(0, 0); CP_COMMIT();
    prefetchB(1, 1); CP_COMMIT();

    // ---- A prologue: LDG x slice, convert bf16, store swizzled A-full; sumsq ----
    {
        const int m  = tid >> 2;   // t-row within tile
        const int sg = tid & 3;    // k-subgroup of 16
        float ss = 0.f;
        for (int kc = 0; kc < 8; ++kc) {
            const float* xc = x + ((size_t)n*D + kc*64 + 16*sg)*T + t0 + m;
            float v[16];
            #pragma unroll
            for (int j = 0; j < 16; ++j) v[j] = xc[(size_t)j*T];
            #pragma unroll
            for (int j = 0; j < 16; ++j) ss = fmaf(v[j], v[j], ss);
            uint32_t pk[8];
            #pragma unroll
            for (int jp = 0; jp < 8; ++jp) {
                __nv_bfloat16 a = __float2bfloat16_rn(v[2*jp]);
                __nv_bfloat16 b = __float2bfloat16_rn(v[2*jp+1]);
                pk[jp] = (uint32_t)__bfloat16_as_ushort(a) | ((uint32_t)__bfloat16_as_ushort(b) << 16);
            }
            char* arow = smem + SM_AFULL + kc*8192 + m*128;
            int seg0 = (2*sg) ^ (m & 7);
            int seg1 = (2*sg+1) ^ (m & 7);
            *reinterpret_cast<uint4*>(arow + seg0*16) = make_uint4(pk[0], pk[1], pk[2], pk[3]);
            *reinterpret_cast<uint4*>(arow + seg1*16) = make_uint4(pk[4], pk[5], pk[6], pk[7]);
        }
        part_s[sg*64 + m] = ss;
    }
    __syncthreads();
    if (tid < M_TILE) {   // fixed-order combine -> deterministic
        float sq = part_s[tid] + part_s[64+tid] + part_s[128+tid] + part_s[192+tid];
        sq_s[tid]  = sq;
        inv_s[tid] = 1.0f / fmaxf(sqrtf(sq), 1e-12f);
    }

    // per-slot running top-2 (2 row-slots per thread)
    float bs1[2], bs2[2]; int bi1[2], bi2[2];
    #pragma unroll
    for (int s = 0; s < 2; ++s) { bs1[s] = 3.4e38f; bs2[s] = 3.4e38f; bi1[s] = 0; bi2[s] = 0; }

    float acc[8][4];
    #pragma unroll
    for (int b = 0; b < 8; ++b)
        #pragma unroll
        for (int e = 0; e < 4; ++e) acc[b][e] = 0.f;

    // fragment address bases
    const int rA = wm*16 + (lane & 7) + ((lane >> 3) & 1)*8;
    const uint32_t rowA = (uint32_t)rA * 128;
    const uint32_t kxA  = ((uint32_t)(lane >> 4)) * 16;
    const uint32_t swA  = ((uint32_t)(rA & 7)) * 16;
    const int rBl = (lane & 7) + ((lane >> 4) & 1)*8;
    const uint32_t kxB  = (((uint32_t)(lane >> 3)) & 1) * 16;
    const uint32_t swB  = ((uint32_t)(lane & 7)) * 16;
    const uint32_t rowB = (uint32_t)(wn*64 + rBl) * 128;

    // ---- mainloop: 4 passes x 8 k-chunks, B double-buffered (wait THEN sync) ----
    for (int c = 0; c < 32; ++c) {
        const int kc = c & 7;
        CP_WAIT1();                    // my group c complete
        __syncthreads();               // all threads' group c complete
        uint32_t bb = sb + SM_BST + (c & 1)*B_STAGE;
        uint32_t aBase = sb + SM_AFULL + kc*8192;

        #pragma unroll
        for (int ks = 0; ks < 4; ++ks) {
            uint32_t bh[4][4];
            #pragma unroll
            for (int nt2 = 0; nt2 < 4; ++nt2)
                ldsm4(bh[nt2], bb + rowB + (uint32_t)nt2*2048 + (((uint32_t)ks*32 + kxB) ^ swB));
            uint32_t aa[4];
            ldsm4(aa, aBase + rowA + (((uint32_t)ks*32 + kxA) ^ swA));
            #pragma unroll
            for (int nt2 = 0; nt2 < 4; ++nt2) {
                mma_bf16(acc[2*nt2],   aa, bh[nt2][0], bh[nt2][1]);
                mma_bf16(acc[2*nt2+1], aa, bh[nt2][2], bh[nt2][3]);
            }
        }

        if (kc == 7) {   // end of pass: fold 128 codes into running top-2
            const int n0 = (c >> 3) * 128;
            #pragma unroll
            for (int h = 0; h < 2; ++h) {
                const int row = wm*16 + (lane >> 2) + h*8;
                const float m2inv = -2.0f * inv_s[row];
                #pragma unroll
                for (int nt = 0; nt < 8; ++nt) {
                    int code = n0 + wn*64 + nt*8 + (lane & 3)*2;
                    float s0 = fmaf(m2inv, acc[nt][h*2+0], cn_s[code]);
                    float s1 = fmaf(m2inv, acc[nt][h*2+1], cn_s[code+1]);
                    if (s0 < bs1[h]) { bs2[h]=bs1[h]; bi2[h]=bi1[h]; bs1[h]=s0; bi1[h]=code; }
                    else if (s0 < bs2[h]) { bs2[h]=s0; bi2[h]=code; }
                    if (s1 < bs1[h]) { bs2[h]=bs1[h]; bi2[h]=bi1[h]; bs1[h]=s1; bi1[h]=code+1; }
                    else if (s1 < bs2[h]) { bs2[h]=s1; bi2[h]=code+1; }
                }
            }
            #pragma unroll
            for (int b = 0; b < 8; ++b)
                #pragma unroll
                for (int e = 0; e < 4; ++e) acc[b][e] = 0.f;
        }

        __syncthreads();               // readers of stage c&1 done before overwrite
        if (c + 2 < 32) { prefetchB(c + 2, c & 1); }
        CP_COMMIT();
    }

    // ---- candidate reduction: 8 slices x top-2 = 16 candidates/row ----
    __syncthreads();
    #pragma unroll
    for (int h = 0; h < 2; ++h) {
        const int row = wm*16 + (lane >> 2) + h*8;
        const int cb = (wn*4 + (lane & 3))*2;
        red_s[row*16 + cb]     = bs1[h]; red_i[row*16 + cb]     = bi1[h];
        red_s[row*16 + cb + 1] = bs2[h]; red_i[row*16 + cb + 1] = bi2[h];
    }
    __syncthreads();

    if (tid < M_TILE) {
        float s1 = 3.4e38f, s2 = s1, s3 = s1, s4 = s1;
        int i1 = 0, i2 = 0, i3 = 0, i4 = 0;
        #pragma unroll
        for (int c = 0; c < 16; ++c) {
            float s = red_s[tid*16 + c]; int ii = red_i[tid*16 + c];
            if (s < s1 || (s == s1 && ii < i1)) { s4=s3;i4=i3; s3=s2;i3=i2; s2=s1;i2=i1; s1=s;i1=ii; }
            else if (s < s2 || (s == s2 && ii < i2)) { s4=s3;i4=i3; s3=s2;i3=i2; s2=s;i2=ii; }
            else if (s < s3 || (s == s3 && ii < i3)) { s4=s3;i4=i3; s3=s;i3=ii; }
            else if (s < s4 || (s == s4 && ii < i4)) { s4=s;i4=ii; }
        }
        idx4_s[tid*4+0] = i1; idx4_s[tid*4+1] = i2;
        idx4_s[tid*4+2] = i3; idx4_s[tid*4+3] = i4;
        flag_s[tid] = (s2 - s1 < 3e-3f) ? 1 : 0;
        provS[tid] = s1; provI[tid] = i1;
    }
    __syncthreads();

    // ---- parallel exact-fp32 rescue: 4 threads per row, one candidate each ----
    {
        const int row = tid & 63, cnd = tid >> 6;
        if (flag_s[row]) {
            int ic = idx4_s[row*4 + cnd];
            const float* xr = x + (size_t)n*D*T + t0 + row;
            const float* cp = codebook + (size_t)ic*D;
            float dacc = 0.f;
            #pragma unroll 8
            for (int d = 0; d < D; ++d) dacc = fmaf(xr[(size_t)d*T], cp[d], dacc);
            dres_s[row*4 + cnd] = fmaf(-2.0f*inv_s[row], dacc, cn_s[ic]);
        }
    }
    __syncthreads();

    if (tid < M_TILE) {
        float bestS = provS[tid]; int bestI = provI[tid];
        if (flag_s[tid]) {
            bestS = dres_s[tid*4]; bestI = idx4_s[tid*4];
            #pragma unroll
            for (int cnd = 1; cnd < 4; ++cnd) {
                float e = dres_s[tid*4 + cnd]; int ii = idx4_s[tid*4 + cnd];
                if (e < bestS || (e == bestS && ii < bestI)) { bestS = e; bestI = ii; }
            }
        }
        idx_s[tid] = bestI;
        cm_s[tid] = fmaf(sq_s[tid]*inv_s[tid], inv_s[tid], bestS);
        atomicAdd(&g_hist[bestI], 1);
    }
    __syncthreads();
    if (tid == 0) {
        float s = 0.f;
        for (int i = 0; i < M_TILE; ++i) s += cm_s[i];
        g_blockCommit[blk] = s;
    }

    // ---- fused output: gather + register transpose + coalesced write ----
    {
        const int mq = tid & 15;      // t-quad
        const int dg = tid >> 4;      // d-group of 4
        int r0i = idx_s[4*mq + 0], r1i = idx_s[4*mq + 1];
        int r2i = idx_s[4*mq + 2], r3i = idx_s[4*mq + 3];
        #pragma unroll
        for (int dt = 0; dt < 8; ++dt) {
            const int d0 = dt*64 + dg*4;
            float4 a = *reinterpret_cast<const float4*>(codebook + (size_t)r0i*D + d0);
            float4 b = *reinterpret_cast<const float4*>(codebook + (size_t)r1i*D + d0);
            float4 cc = *reinterpret_cast<const float4*>(codebook + (size_t)r2i*D + d0);
            float4 dd = *reinterpret_cast<const float4*>(codebook + (size_t)r3i*D + d0);
            float* ob = out + ((size_t)n*D + d0)*T + t0 + 4*mq;
            *reinterpret_cast<float4*>(ob)              = make_float4(a.x, b.x, cc.x, dd.x);
            *reinterpret_cast<float4*>(ob + T)          = make_float4(a.y, b.y, cc.y, dd.y);
            *reinterpret_cast<float4*>(ob + 2*(size_t)T)= make_float4(a.z, b.z, cc.z, dd.z);
            *reinterpret_cast<float4*>(ob + 3*(size_t)T)= make_float4(a.w, b.w, cc.w, dd.w);
        }
    }
}

// ---------------- finalize: perplexity + commit mean ----------------
__global__ void finalize_kernel(float* __restrict__ out) {
    __shared__ double sbuf[512];
    int t = threadIdx.x;
    float prob = (float)g_hist[t] / 65536.0f;
    sbuf[t] = (double)(prob * logf(prob + 1e-7f));
    __syncthreads();
    for (int s = 256; s > 0; s >>= 1) { if (t < s) sbuf[t] += sbuf[t+s]; __syncthreads(); }
    double psum = sbuf[0];
    __syncthreads();
    double c = 0.0;
    for (int i = t; i < CTAS; i += 512) c += (double)g_blockCommit[i];
    sbuf[t] = c;
    __syncthreads();
    for (int s = 256; s > 0; s >>= 1) { if (t < s) sbuf[t] += sbuf[t+s]; __syncthreads(); }
    if (t == 0) {
        out[(size_t)R*D]     = (float)(sbuf[0] / ((double)R * (double)D));
        out[(size_t)R*D + 1] = expf((float)(-psum));
    }
}

// ---------------- launch ----------------
extern "C" void kernel_launch(void* const* d_in, const int* in_sizes, int n_in,
                              void* d_out, int out_size) {
    const float* x        = (const float*)d_in[0];
    const float* codebook = (const float*)d_in[1];
    float* out = (float*)d_out;

    cudaFuncSetAttribute(vq_main, cudaFuncAttributeMaxDynamicSharedMemorySize, SMEM_TOTAL);

    prep_cb<<<NB, D>>>(codebook);
    vq_main<<<CTAS, 256, SMEM_TOTAL>>>(x, codebook, out);
    finalize_kernel<<<1, 512>>>(out);
}